// round 7
// baseline (speedup 1.0000x reference)
#include <cuda_runtime.h>
#include <cuda_bf16.h>
#include <stdint.h>
#include <math.h>

#define T_TOK 2048
#define HD    2048
#define ID    768
#define NE    64
#define TOPK  8
#define CAPE  512

// ---------------- scratch (device globals) ----------------
__device__ int   g_sel [T_TOK*TOPK];
__device__ float g_wsel[T_TOK*TOPK];
__device__ int   g_slot[T_TOK*TOPK];
__device__ int   g_tok [NE*CAPE];
__device__ float g_wslot[NE*CAPE];
__device__ int   g_cnt [NE];
__device__ float g_logits[T_TOK*NE];
__device__ __nv_bfloat16 g_xh[(size_t)T_TOK*HD],  g_xl[(size_t)T_TOK*HD];
__device__ __nv_bfloat16 g_hh[(size_t)NE*CAPE*ID], g_hl[(size_t)NE*CAPE*ID];

// ---------------- helpers ----------------
__device__ __forceinline__ uint32_t s2u(const void* p) {
    uint32_t a;
    asm("{ .reg .u64 t; cvta.to.shared.u64 t, %1; cvt.u32.u64 %0, t; }" : "=r"(a) : "l"(p));
    return a;
}
__device__ __forceinline__ uint32_t sw(uint32_t off) {   // Swizzle<3,4,3> on flat bytes
    return off ^ (((off >> 7) & 7u) << 4);
}
__device__ __forceinline__ void cpa(uint32_t d, const void* s, int nb) {
    asm volatile("cp.async.cg.shared.global [%0], [%1], 16, %2;"
                 :: "r"(d), "l"(s), "r"(nb) : "memory");
}
#define CP_COMMIT() asm volatile("cp.async.commit_group;" ::: "memory")
#define CP_WAIT2()  asm volatile("cp.async.wait_group 2;" ::: "memory")

__device__ __forceinline__ void ldsm4(uint32_t& r0, uint32_t& r1, uint32_t& r2, uint32_t& r3, uint32_t a) {
    asm volatile("ldmatrix.sync.aligned.m8n8.x4.shared.b16 {%0,%1,%2,%3}, [%4];"
                 : "=r"(r0), "=r"(r1), "=r"(r2), "=r"(r3) : "r"(a));
}
__device__ __forceinline__ void ldsm4t(uint32_t& r0, uint32_t& r1, uint32_t& r2, uint32_t& r3, uint32_t a) {
    asm volatile("ldmatrix.sync.aligned.m8n8.x4.trans.shared.b16 {%0,%1,%2,%3}, [%4];"
                 : "=r"(r0), "=r"(r1), "=r"(r2), "=r"(r3) : "r"(a));
}
__device__ __forceinline__ void mma16816(float* c, const uint32_t* a, const uint32_t* b) {
    asm volatile("mma.sync.aligned.m16n8k16.row.col.f32.bf16.bf16.f32 "
                 "{%0,%1,%2,%3}, {%4,%5,%6,%7}, {%8,%9}, {%0,%1,%2,%3};"
                 : "+f"(c[0]), "+f"(c[1]), "+f"(c[2]), "+f"(c[3])
                 : "r"(a[0]), "r"(a[1]), "r"(a[2]), "r"(a[3]), "r"(b[0]), "r"(b[1]));
}
// split 8 fp32 -> 8 bf16 hi + 8 bf16 lo (packed as uint4 each)
__device__ __forceinline__ void split8(float4 a, float4 b, uint4& hi, uint4& lo) {
    __nv_bfloat162 h0 = __floats2bfloat162_rn(a.x, a.y);
    __nv_bfloat162 h1 = __floats2bfloat162_rn(a.z, a.w);
    __nv_bfloat162 h2 = __floats2bfloat162_rn(b.x, b.y);
    __nv_bfloat162 h3 = __floats2bfloat162_rn(b.z, b.w);
    __nv_bfloat162 l0 = __floats2bfloat162_rn(a.x - __low2float(h0), a.y - __high2float(h0));
    __nv_bfloat162 l1 = __floats2bfloat162_rn(a.z - __low2float(h1), a.w - __high2float(h1));
    __nv_bfloat162 l2 = __floats2bfloat162_rn(b.x - __low2float(h2), b.y - __high2float(h2));
    __nv_bfloat162 l3 = __floats2bfloat162_rn(b.z - __low2float(h3), b.w - __high2float(h3));
    hi = make_uint4(*(uint32_t*)&h0, *(uint32_t*)&h1, *(uint32_t*)&h2, *(uint32_t*)&h3);
    lo = make_uint4(*(uint32_t*)&l0, *(uint32_t*)&l1, *(uint32_t*)&l2, *(uint32_t*)&l3);
}

// ---------------- x conversion: fp32 -> bf16 hi/lo ----------------
__global__ void convert_x_kernel(const float* __restrict__ src, int n4) {
    for (int i = blockIdx.x*blockDim.x + threadIdx.x; i < n4; i += gridDim.x*blockDim.x) {
        float4 v = ((const float4*)src)[i];
        __nv_bfloat162 a  = __floats2bfloat162_rn(v.x, v.y);
        __nv_bfloat162 b  = __floats2bfloat162_rn(v.z, v.w);
        __nv_bfloat162 ra = __floats2bfloat162_rn(v.x - __low2float(a), v.y - __high2float(a));
        __nv_bfloat162 rb = __floats2bfloat162_rn(v.z - __low2float(b), v.w - __high2float(b));
        ((uint2*)g_xh)[i] = make_uint2(*(uint32_t*)&a,  *(uint32_t*)&b);
        ((uint2*)g_xl)[i] = make_uint2(*(uint32_t*)&ra, *(uint32_t*)&rb);
    }
}

// ---------------- zero y ----------------
__global__ void zero_y_kernel(float* __restrict__ y) {
    int i = blockIdx.x*blockDim.x + threadIdx.x;
    ((float4*)y)[i] = make_float4(0.f, 0.f, 0.f, 0.f);
}

// ---------------- gate logits ----------------
__global__ __launch_bounds__(256) void gate_kernel(const float* __restrict__ x,
                                                   const float* __restrict__ gw) {
    const int t0  = blockIdx.x * 32;
    const int tid = threadIdx.x;
    __shared__ float sx[32][33];
    __shared__ float swt[32][65];
    float acc[8];
    #pragma unroll
    for (int i = 0; i < 8; i++) acc[i] = 0.f;
    const int e  = tid & 63;
    const int tb = tid >> 6;
    for (int k0 = 0; k0 < HD; k0 += 32) {
        #pragma unroll
        for (int j = 0; j < 4; j++) {
            int item = tid + j*256;
            int r = item >> 5, c = item & 31;
            sx[r][c] = x[(size_t)(t0 + r)*HD + k0 + c];
        }
        #pragma unroll
        for (int j = 0; j < 8; j++) {
            int item = tid + j*256;
            int ee = item >> 5, hh = item & 31;
            swt[hh][ee] = gw[(size_t)ee*HD + k0 + hh];
        }
        __syncthreads();
        #pragma unroll
        for (int hh = 0; hh < 32; hh++) {
            float wv = swt[hh][e];
            #pragma unroll
            for (int i = 0; i < 8; i++)
                acc[i] += sx[tb*8 + i][hh] * wv;
        }
        __syncthreads();
    }
    #pragma unroll
    for (int i = 0; i < 8; i++)
        g_logits[(size_t)(t0 + tb*8 + i)*NE + e] = acc[i];
}

// ---------------- top-8 ----------------
__global__ void topk_kernel() {
    const int t = blockIdx.x, tid = threadIdx.x;
    __shared__ float sp[64];
    sp[tid] = g_logits[(size_t)t*NE + tid];
    __syncthreads();
    if (tid == 0) {
        float mx = sp[0];
        for (int i = 1; i < 64; i++) mx = fmaxf(mx, sp[i]);
        for (int i = 0; i < 64; i++) sp[i] = expf(sp[i] - mx);
        int idx8[8]; float w8[8]; float s8 = 0.f;
        for (int r = 0; r < 8; r++) {
            float best = -1.f; int bi = 0;
            for (int i = 0; i < 64; i++)
                if (sp[i] > best) { best = sp[i]; bi = i; }
            idx8[r] = bi; w8[r] = best; s8 += best; sp[bi] = -1.f;
        }
        float inv = 1.f / s8;
        for (int r = 0; r < 8; r++) {
            g_sel [t*TOPK + r] = idx8[r];
            g_wsel[t*TOPK + r] = w8[r] * inv;
        }
    }
}

// ---------------- routing (exact prefix order) ----------------
__global__ void route_kernel() {
    const int e = blockIdx.x;
    const int tid = threadIdx.x;
    for (int s = tid; s < CAPE; s += 256) { g_tok[e*CAPE + s] = -1; g_wslot[e*CAPE + s] = 0.f; }
    __shared__ int wsum[8];
    __shared__ int sbase;
    if (tid == 0) sbase = 0;
    __syncthreads();
    const int lane = tid & 31, wid = tid >> 5;
    for (int c = 0; c < T_TOK*TOPK; c += 256) {
        int i = c + tid;
        int ei = g_sel[i];
        bool flag = (ei == e);
        unsigned mask = __ballot_sync(0xffffffffu, flag);
        int wpre = __popc(mask & ((1u << lane) - 1u));
        if (lane == 0) wsum[wid] = __popc(mask);
        __syncthreads();
        int off = 0;
        for (int w = 0; w < wid; w++) off += wsum[w];
        int total = 0;
        for (int w = 0; w < 8; w++) total += wsum[w];
        int pos = sbase + off + wpre;
        if (flag) {
            if (pos < CAPE) {
                g_slot[i] = pos;
                g_tok[e*CAPE + pos] = i / TOPK;
                g_wslot[e*CAPE + pos] = g_wsel[i];
            } else {
                g_slot[i] = -1;
            }
        }
        __syncthreads();
        if (tid == 0) sbase += total;
        __syncthreads();
    }
    if (tid == 0) g_cnt[e] = min(sbase, CAPE);
}

// ================= GEMM1: h = silu(A@Wg)*(A@Wu), bf16 3-term =================
// CTA: M=128, N=64. K-chunks of 32, 4-stage A cp.async + register-prefetch fp32 B.
// Stage (32KB): AH@0(8K) AL@8192 GH@16384(4K) GL@20480 UH@24576 UL@28672
#define STG 32768
#define G_SMEM (2048 + 4*STG)

__global__ __launch_bounds__(256, 1) void gemm1_kernel(const float* __restrict__ wgp,
                                                       const float* __restrict__ wup) {
    const int e  = blockIdx.z;
    const int m0 = blockIdx.y * 128;
    const int n0 = blockIdx.x * 64;
    if (m0 >= g_cnt[e]) return;

    extern __shared__ __align__(1024) char smem_raw[];
    const uint32_t su = s2u(smem_raw);
    const uint32_t tb = (su + 2048 + 1023) & ~1023u;
    int* sTok = (int*)smem_raw;

    const int tid = threadIdx.x;
    if (tid < 128) sTok[tid] = g_tok[e*CAPE + m0 + tid];
    __syncthreads();

    // ---- A staging map (cp.async from bf16 hi/lo x) ----
    const int mA  = tid >> 2, kcA = tid & 3;
    const uint32_t dA0 = sw((uint32_t)(mA*64      + kcA*16));
    const uint32_t dA1 = sw((uint32_t)((mA+64)*64 + kcA*16));
    const int tk0 = sTok[mA], tk1 = sTok[mA+64];
    const int nb0 = tk0 >= 0 ? 16 : 0, nb1 = tk1 >= 0 ? 16 : 0;
    const __nv_bfloat16* ah0 = g_xh + (size_t)(tk0 >= 0 ? tk0 : 0)*HD + kcA*8;
    const __nv_bfloat16* al0 = g_xl + (size_t)(tk0 >= 0 ? tk0 : 0)*HD + kcA*8;
    const __nv_bfloat16* ah1 = g_xh + (size_t)(tk1 >= 0 ? tk1 : 0)*HD + kcA*8;
    const __nv_bfloat16* al1 = g_xl + (size_t)(tk1 >= 0 ? tk1 : 0)*HD + kcA*8;

    auto issueA = [&](int it) {
        const int k0 = it * 32;
        const uint32_t sb = tb + (uint32_t)(it & 3) * STG;
        cpa(sb + dA0,        ah0 + k0, nb0);
        cpa(sb + 8192 + dA0, al0 + k0, nb0);
        cpa(sb + dA1,        ah1 + k0, nb1);
        cpa(sb + 8192 + dA1, al1 + k0, nb1);
        CP_COMMIT();
    };

    // ---- B staging: fp32 LDG prefetch -> split -> STS ----
    const int kB = tid >> 3, ncB = tid & 7;                 // 32 rows x 8 col-chunks
    const uint32_t dB = sw((uint32_t)(kB*128 + ncB*16));
    const size_t bOff = (size_t)e*HD*ID + (size_t)kB*ID + n0 + ncB*8;
    const int NIT = HD / 32;

    float4 pg[2][2], pu[2][2];
    auto ldgB = [&](int it, int set) {
        if (it < NIT) {
            const float* pgp = wgp + bOff + (size_t)it*32*ID;
            const float* pup = wup + bOff + (size_t)it*32*ID;
            pg[set][0] = ((const float4*)pgp)[0]; pg[set][1] = ((const float4*)pgp)[1];
            pu[set][0] = ((const float4*)pup)[0]; pu[set][1] = ((const float4*)pup)[1];
        }
    };
    auto stsB = [&](int it, int set) {
        if (it < NIT) {
            const uint32_t sb = tb + (uint32_t)(it & 3) * STG;
            uint4 hi, lo;
            split8(pg[set][0], pg[set][1], hi, lo);
            *(uint4*)(smem_raw + (sb - su) + 16384 + dB) = hi;
            *(uint4*)(smem_raw + (sb - su) + 20480 + dB) = lo;
            split8(pu[set][0], pu[set][1], hi, lo);
            *(uint4*)(smem_raw + (sb - su) + 24576 + dB) = hi;
            *(uint4*)(smem_raw + (sb - su) + 28672 + dB) = lo;
        }
    };

    // ---- compute maps ----
    const int lane = tid & 31, wid = tid >> 5;
    const int wm = wid >> 1, wn = wid & 1;
    uint32_t offA[2][2], offB[2][2];
    #pragma unroll
    for (int tm = 0; tm < 2; tm++)
        #pragma unroll
        for (int ks = 0; ks < 2; ks++)
            offA[tm][ks] = sw((uint32_t)((wm*32 + tm*16 + (lane & 15))*64 + ks*32 + (lane >> 4)*16));
    #pragma unroll
    for (int ks = 0; ks < 2; ks++)
        #pragma unroll
        for (int nh = 0; nh < 2; nh++)
            offB[ks][nh] = sw((uint32_t)((ks*16 + (lane & 15))*128 + wn*64 + nh*32 + (lane >> 4)*16));

    float cG[2][4][4], cU[2][4][4];
    #pragma unroll
    for (int a = 0; a < 2; a++)
        #pragma unroll
        for (int b = 0; b < 4; b++)
            #pragma unroll
            for (int c = 0; c < 4; c++) { cG[a][b][c] = 0.f; cU[a][b][c] = 0.f; }

    // prologue: B(0..2) direct, B(3),B(4) prefetched; A(0..2) async
    #pragma unroll
    for (int it = 0; it < 3; it++) { ldgB(it, 0); stsB(it, 0); }
    ldgB(3, 0); ldgB(4, 1);
    issueA(0); issueA(1); issueA(2);

    #pragma unroll 1
    for (int it = 0; it < NIT; it++) {
        CP_WAIT2();
        __syncthreads();
        stsB(it + 3, it & 1);
        ldgB(it + 5, it & 1);
        if (it + 3 < NIT) issueA(it + 3);
        else CP_COMMIT();
        const uint32_t sb = tb + (uint32_t)(it & 3) * STG;
        #pragma unroll
        for (int ks = 0; ks < 2; ks++) {
            uint32_t aH[2][4], aL[2][4];
            #pragma unroll
            for (int tm = 0; tm < 2; tm++) {
                ldsm4(aH[tm][0], aH[tm][1], aH[tm][2], aH[tm][3], sb + offA[tm][ks]);
                ldsm4(aL[tm][0], aL[tm][1], aL[tm][2], aL[tm][3], sb + 8192 + offA[tm][ks]);
            }
            {   // G
                uint32_t bh[4][2], bl[4][2];
                #pragma unroll
                for (int nh = 0; nh < 2; nh++) {
                    ldsm4t(bh[nh*2][0], bh[nh*2][1], bh[nh*2+1][0], bh[nh*2+1][1], sb + 16384 + offB[ks][nh]);
                    ldsm4t(bl[nh*2][0], bl[nh*2][1], bl[nh*2+1][0], bl[nh*2+1][1], sb + 20480 + offB[ks][nh]);
                }
                #pragma unroll
                for (int tm = 0; tm < 2; tm++)
                    #pragma unroll
                    for (int tn = 0; tn < 4; tn++) {
                        mma16816(cG[tm][tn], aH[tm], bh[tn]);
                        mma16816(cG[tm][tn], aL[tm], bh[tn]);
                        mma16816(cG[tm][tn], aH[tm], bl[tn]);
                    }
            }
            {   // U
                uint32_t bh[4][2], bl[4][2];
                #pragma unroll
                for (int nh = 0; nh < 2; nh++) {
                    ldsm4t(bh[nh*2][0], bh[nh*2][1], bh[nh*2+1][0], bh[nh*2+1][1], sb + 24576 + offB[ks][nh]);
                    ldsm4t(bl[nh*2][0], bl[nh*2][1], bl[nh*2+1][0], bl[nh*2+1][1], sb + 28672 + offB[ks][nh]);
                }
                #pragma unroll
                for (int tm = 0; tm < 2; tm++)
                    #pragma unroll
                    for (int tn = 0; tn < 4; tn++) {
                        mma16816(cU[tm][tn], aH[tm], bh[tn]);
                        mma16816(cU[tm][tn], aL[tm], bh[tn]);
                        mma16816(cU[tm][tn], aH[tm], bl[tn]);
                    }
            }
        }
    }

    // epilogue: h = silu(G)*U -> bf16 hi/lo
    const int r4 = lane >> 2, cp2 = (lane & 3) * 2;
    #pragma unroll
    for (int tm = 0; tm < 2; tm++)
        #pragma unroll
        for (int tn = 0; tn < 4; tn++) {
            const int row0 = m0 + wm*32 + tm*16 + r4;
            const int col  = n0 + wn*32 + tn*8 + cp2;
            #pragma unroll
            for (int half = 0; half < 2; half++) {
                float g0 = cG[tm][tn][half*2],     u0 = cU[tm][tn][half*2];
                float g1 = cG[tm][tn][half*2 + 1], u1 = cU[tm][tn][half*2 + 1];
                float h0 = g0 / (1.f + __expf(-g0)) * u0;
                float h1 = g1 / (1.f + __expf(-g1)) * u1;
                __nv_bfloat162 hh = __floats2bfloat162_rn(h0, h1);
                __nv_bfloat162 ll = __floats2bfloat162_rn(h0 - __low2float(hh), h1 - __high2float(hh));
                const size_t o = ((size_t)e*CAPE + row0 + half*8)*ID + col;
                *(uint32_t*)(g_hh + o) = *(uint32_t*)&hh;
                *(uint32_t*)(g_hl + o) = *(uint32_t*)&ll;
            }
        }
}

// ================= GEMM2: y += w * (h @ wd), bf16 3-term, scatter-add =================
// CTA: M=128, N=128 (2 slabs of 64). Stage (32KB): AH@0 AL@8192 BH@16384 BL@24576
__global__ __launch_bounds__(256, 1) void gemm2_kernel(const float* __restrict__ wdp,
                                                       float* __restrict__ y) {
    const int e  = blockIdx.z;
    const int m0 = blockIdx.y * 128;
    const int n0 = blockIdx.x * 128;
    if (m0 >= g_cnt[e]) return;

    extern __shared__ __align__(1024) char smem_raw[];
    const uint32_t su = s2u(smem_raw);
    const uint32_t tb = (su + 2048 + 1023) & ~1023u;
    int*   sTok = (int*)smem_raw;
    float* sW   = (float*)(smem_raw + 512);
    const int tid = threadIdx.x;
    if (tid < 128) {
        sTok[tid] = g_tok  [e*CAPE + m0 + tid];
        sW[tid]   = g_wslot[e*CAPE + m0 + tid];
    }
    __syncthreads();

    // ---- A staging (cp.async from bf16 h hi/lo) ----
    const int mA = tid >> 2, kcA = tid & 3;
    const uint32_t dA0 = sw((uint32_t)(mA*64      + kcA*16));
    const uint32_t dA1 = sw((uint32_t)((mA+64)*64 + kcA*16));

    auto issueA = [&](int it) {
        const int k0 = it * 32;
        const uint32_t sb = tb + (uint32_t)(it & 3) * STG;
        const size_t ga0 = ((size_t)e*CAPE + m0 + mA)*ID + k0 + kcA*8;
        const size_t ga1 = ((size_t)e*CAPE + m0 + mA + 64)*ID + k0 + kcA*8;
        cpa(sb + dA0,        g_hh + ga0, 16);
        cpa(sb + 8192 + dA0, g_hl + ga0, 16);
        cpa(sb + dA1,        g_hh + ga1, 16);
        cpa(sb + 8192 + dA1, g_hl + ga1, 16);
        CP_COMMIT();
    };

    // ---- B staging: fp32 wd prefetch -> split -> STS ----
    const int kB0 = tid >> 4, ncB0 = tid & 15;   // rows kB0 and kB0+16, col chunk ncB0
    const uint32_t dB0 = (uint32_t)((ncB0 >> 3)*4096) + sw((uint32_t)(kB0*128 + (ncB0 & 7)*16));
    const uint32_t dB1 = (uint32_t)((ncB0 >> 3)*4096) + sw((uint32_t)((kB0+16)*128 + (ncB0 & 7)*16));
    const size_t bOff = (size_t)e*ID*HD + (size_t)kB0*HD + n0 + ncB0*8;
    const int NIT = ID / 32;

    float4 pb[2][2][2];   // [set][row-half][float4]
    auto ldgB = [&](int it, int set) {
        if (it < NIT) {
            const float* p0 = wdp + bOff + (size_t)it*32*HD;
            const float* p1 = p0 + (size_t)16*HD;
            pb[set][0][0] = ((const float4*)p0)[0]; pb[set][0][1] = ((const float4*)p0)[1];
            pb[set][1][0] = ((const float4*)p1)[0]; pb[set][1][1] = ((const float4*)p1)[1];
        }
    };
    auto stsB = [&](int it, int set) {
        if (it < NIT) {
            const uint32_t off = (uint32_t)(it & 3) * STG + (tb - su);
            uint4 hi, lo;
            split8(pb[set][0][0], pb[set][0][1], hi, lo);
            *(uint4*)(smem_raw + off + 16384 + dB0) = hi;
            *(uint4*)(smem_raw + off + 24576 + dB0) = lo;
            split8(pb[set][1][0], pb[set][1][1], hi, lo);
            *(uint4*)(smem_raw + off + 16384 + dB1) = hi;
            *(uint4*)(smem_raw + off + 24576 + dB1) = lo;
        }
    };

    const int lane = tid & 31, wid = tid >> 5;
    const int wm = wid >> 1, wn = wid & 1;   // warp tile 32 rows x 64 cols
    uint32_t offA[2][2], offB[2][4];
    #pragma unroll
    for (int tm = 0; tm < 2; tm++)
        #pragma unroll
        for (int ks = 0; ks < 2; ks++)
            offA[tm][ks] = sw((uint32_t)((wm*32 + tm*16 + (lane & 15))*64 + ks*32 + (lane >> 4)*16));
    #pragma unroll
    for (int ks = 0; ks < 2; ks++)
        #pragma unroll
        for (int nh = 0; nh < 4; nh++)
            offB[ks][nh] = (uint32_t)(wn*4096) +
                           sw((uint32_t)((ks*16 + (lane & 15))*128 + nh*32 + (lane >> 4)*16));

    float cc[2][8][4];
    #pragma unroll
    for (int a = 0; a < 2; a++)
        #pragma unroll
        for (int b = 0; b < 8; b++)
            #pragma unroll
            for (int c = 0; c < 4; c++) cc[a][b][c] = 0.f;

    #pragma unroll
    for (int it = 0; it < 3; it++) { ldgB(it, 0); stsB(it, 0); }
    ldgB(3, 0); ldgB(4, 1);
    issueA(0); issueA(1); issueA(2);

    #pragma unroll 1
    for (int it = 0; it < NIT; it++) {
        CP_WAIT2();
        __syncthreads();
        stsB(it + 3, it & 1);
        ldgB(it + 5, it & 1);
        if (it + 3 < NIT) issueA(it + 3);
        else CP_COMMIT();
        const uint32_t sb = tb + (uint32_t)(it & 3) * STG;
        #pragma unroll
        for (int ks = 0; ks < 2; ks++) {
            uint32_t aH[2][4], aL[2][4];
            #pragma unroll
            for (int tm = 0; tm < 2; tm++) {
                ldsm4(aH[tm][0], aH[tm][1], aH[tm][2], aH[tm][3], sb + offA[tm][ks]);
                ldsm4(aL[tm][0], aL[tm][1], aL[tm][2], aL[tm][3], sb + 8192 + offA[tm][ks]);
            }
            uint32_t bh[8][2], bl[8][2];
            #pragma unroll
            for (int nh = 0; nh < 4; nh++) {
                ldsm4t(bh[nh*2][0], bh[nh*2][1], bh[nh*2+1][0], bh[nh*2+1][1], sb + 16384 + offB[ks][nh]);
                ldsm4t(bl[nh*2][0], bl[nh*2][1], bl[nh*2+1][0], bl[nh*2+1][1], sb + 24576 + offB[ks][nh]);
            }
            #pragma unroll
            for (int tm = 0; tm < 2; tm++)
                #pragma unroll
                for (int tn = 0; tn < 8; tn++) {
                    mma16816(cc[tm][tn], aH[tm], bh[tn]);
                    mma16816(cc[tm][tn], aL[tm], bh[tn]);
                    mma16816(cc[tm][tn], aH[tm], bl[tn]);
                }
        }
    }

    // epilogue: scatter-add w * out into y
    const int r4 = lane >> 2, cp2 = (lane & 3) * 2;
    #pragma unroll
    for (int tm = 0; tm < 2; tm++)
        #pragma unroll
        for (int tn = 0; tn < 8; tn++) {
            const int col = n0 + wn*64 + tn*8 + cp2;
            #pragma unroll
            for (int half = 0; half < 2; half++) {
                const int rloc = wm*32 + tm*16 + r4 + half*8;
                const int tok = sTok[rloc];
                if (tok < 0) continue;
                const float w = sW[rloc];
                float* yp = y + (size_t)tok*HD + col;
                atomicAdd(yp,     w * cc[tm][tn][half*2]);
                atomicAdd(yp + 1, w * cc[tm][tn][half*2 + 1]);
            }
        }
}

// ---------------- launch ----------------
extern "C" void kernel_launch(void* const* d_in, const int* in_sizes, int n_in,
                              void* d_out, int out_size) {
    const float* x      = (const float*)d_in[0];
    const float* gate_w = (const float*)d_in[1];
    const float* wg     = (const float*)d_in[2];
    const float* wu     = (const float*)d_in[3];
    const float* wd     = (const float*)d_in[4];
    float* y = (float*)d_out;

    cudaFuncSetAttribute(gemm1_kernel, cudaFuncAttributeMaxDynamicSharedMemorySize, G_SMEM);
    cudaFuncSetAttribute(gemm2_kernel, cudaFuncAttributeMaxDynamicSharedMemorySize, G_SMEM);

    convert_x_kernel<<<1024, 256>>>(x, (T_TOK*HD)/4);
    gate_kernel<<<T_TOK/32, 256>>>(x, gate_w);
    topk_kernel<<<T_TOK, 64>>>();
    route_kernel<<<NE, 256>>>();
    zero_y_kernel<<<(T_TOK*HD)/4/256, 256>>>(y);

    gemm1_kernel<<<dim3(ID/64,  CAPE/128, NE), 256, G_SMEM>>>(wg, wu);
    gemm2_kernel<<<dim3(HD/128, CAPE/128, NE), 256, G_SMEM>>>(wd, y);
}

// round 8
// speedup vs baseline: 1.2683x; 1.2683x over previous
#include <cuda_runtime.h>
#include <cuda_bf16.h>
#include <stdint.h>
#include <math.h>

#define T_TOK 2048
#define HD    2048
#define ID    768
#define NE    64
#define TOPK  8
#define CAPE  512

// ---------------- scratch (device globals) ----------------
__device__ int   g_sel [T_TOK*TOPK];
__device__ float g_wsel[T_TOK*TOPK];
__device__ int   g_tok [NE*CAPE];
__device__ float g_wslot[NE*CAPE];
__device__ int   g_cnt [NE];
__device__ float g_logits[T_TOK*NE];
__device__ __nv_bfloat16 g_xh[(size_t)T_TOK*HD],  g_xl[(size_t)T_TOK*HD];
__device__ __nv_bfloat16 g_wgh[(size_t)NE*HD*ID], g_wgl[(size_t)NE*HD*ID];
__device__ __nv_bfloat16 g_wuh[(size_t)NE*HD*ID], g_wul[(size_t)NE*HD*ID];
__device__ __nv_bfloat16 g_wdh[(size_t)NE*ID*HD], g_wdl[(size_t)NE*ID*HD];
__device__ __nv_bfloat16 g_hh [(size_t)NE*CAPE*ID], g_hl[(size_t)NE*CAPE*ID];

// ---------------- helpers ----------------
__device__ __forceinline__ uint32_t s2u(const void* p) {
    uint32_t a;
    asm("{ .reg .u64 t; cvta.to.shared.u64 t, %1; cvt.u32.u64 %0, t; }" : "=r"(a) : "l"(p));
    return a;
}
__device__ __forceinline__ uint32_t sw(uint32_t off) {   // Swizzle<3,4,3> on flat bytes
    return off ^ (((off >> 7) & 7u) << 4);
}
__device__ __forceinline__ void cpa(uint32_t d, const void* s, int nb) {
    asm volatile("cp.async.cg.shared.global [%0], [%1], 16, %2;"
                 :: "r"(d), "l"(s), "r"(nb) : "memory");
}
#define CP_COMMIT() asm volatile("cp.async.commit_group;" ::: "memory")
#define CP_WAIT2()  asm volatile("cp.async.wait_group 2;" ::: "memory")

__device__ __forceinline__ void ldsm4(uint32_t& r0, uint32_t& r1, uint32_t& r2, uint32_t& r3, uint32_t a) {
    asm volatile("ldmatrix.sync.aligned.m8n8.x4.shared.b16 {%0,%1,%2,%3}, [%4];"
                 : "=r"(r0), "=r"(r1), "=r"(r2), "=r"(r3) : "r"(a));
}
__device__ __forceinline__ void ldsm4t(uint32_t& r0, uint32_t& r1, uint32_t& r2, uint32_t& r3, uint32_t a) {
    asm volatile("ldmatrix.sync.aligned.m8n8.x4.trans.shared.b16 {%0,%1,%2,%3}, [%4];"
                 : "=r"(r0), "=r"(r1), "=r"(r2), "=r"(r3) : "r"(a));
}
__device__ __forceinline__ void mma16816(float* c, const uint32_t* a, const uint32_t* b) {
    asm volatile("mma.sync.aligned.m16n8k16.row.col.f32.bf16.bf16.f32 "
                 "{%0,%1,%2,%3}, {%4,%5,%6,%7}, {%8,%9}, {%0,%1,%2,%3};"
                 : "+f"(c[0]), "+f"(c[1]), "+f"(c[2]), "+f"(c[3])
                 : "r"(a[0]), "r"(a[1]), "r"(a[2]), "r"(a[3]), "r"(b[0]), "r"(b[1]));
}

// ---------------- conversion: fp32 -> bf16 hi/lo ----------------
__global__ void convert_kernel(const float* __restrict__ src, int sel, int n4) {
    __nv_bfloat16 *hi, *lo;
    if      (sel == 0) { hi = g_xh;  lo = g_xl;  }
    else if (sel == 1) { hi = g_wgh; lo = g_wgl; }
    else if (sel == 2) { hi = g_wuh; lo = g_wul; }
    else               { hi = g_wdh; lo = g_wdl; }
    for (int i = blockIdx.x*blockDim.x + threadIdx.x; i < n4; i += gridDim.x*blockDim.x) {
        float4 v = ((const float4*)src)[i];
        __nv_bfloat162 a  = __floats2bfloat162_rn(v.x, v.y);
        __nv_bfloat162 b  = __floats2bfloat162_rn(v.z, v.w);
        __nv_bfloat162 ra = __floats2bfloat162_rn(v.x - __low2float(a), v.y - __high2float(a));
        __nv_bfloat162 rb = __floats2bfloat162_rn(v.z - __low2float(b), v.w - __high2float(b));
        ((uint2*)hi)[i] = make_uint2(*reinterpret_cast<uint32_t*>(&a),  *reinterpret_cast<uint32_t*>(&b));
        ((uint2*)lo)[i] = make_uint2(*reinterpret_cast<uint32_t*>(&ra), *reinterpret_cast<uint32_t*>(&rb));
    }
}

// ---------------- zero y ----------------
__global__ void zero_y_kernel(float* __restrict__ y) {
    int i = blockIdx.x*blockDim.x + threadIdx.x;
    ((float4*)y)[i] = make_float4(0.f, 0.f, 0.f, 0.f);
}

// ---------------- gate logits ----------------
__global__ __launch_bounds__(256) void gate_kernel(const float* __restrict__ x,
                                                   const float* __restrict__ gw) {
    const int t0  = blockIdx.x * 32;
    const int tid = threadIdx.x;
    __shared__ float sx[32][33];
    __shared__ float swt[32][65];
    float acc[8];
    #pragma unroll
    for (int i = 0; i < 8; i++) acc[i] = 0.f;
    const int e  = tid & 63;
    const int tb = tid >> 6;
    for (int k0 = 0; k0 < HD; k0 += 32) {
        #pragma unroll
        for (int j = 0; j < 4; j++) {
            int item = tid + j*256;
            int r = item >> 5, c = item & 31;
            sx[r][c] = x[(size_t)(t0 + r)*HD + k0 + c];
        }
        #pragma unroll
        for (int j = 0; j < 8; j++) {
            int item = tid + j*256;
            int ee = item >> 5, hh = item & 31;
            swt[hh][ee] = gw[(size_t)ee*HD + k0 + hh];
        }
        __syncthreads();
        #pragma unroll
        for (int hh = 0; hh < 32; hh++) {
            float wv = swt[hh][e];
            #pragma unroll
            for (int i = 0; i < 8; i++)
                acc[i] += sx[tb*8 + i][hh] * wv;
        }
        __syncthreads();
    }
    #pragma unroll
    for (int i = 0; i < 8; i++)
        g_logits[(size_t)(t0 + tb*8 + i)*NE + e] = acc[i];
}

// ---------------- parallel top-8 (64 threads / token) ----------------
__global__ void topk_kernel() {
    const int t = blockIdx.x, tid = threadIdx.x;
    const int lane = tid & 31, w = tid >> 5;
    float v = g_logits[(size_t)t*NE + tid];
    __shared__ float swv[2];
    __shared__ int   swi[2];
    __shared__ int   sidx;
    __shared__ float sval[8];
    __shared__ int   ssel[8];
    for (int r = 0; r < 8; r++) {
        float mv = v; int mi = tid;
        #pragma unroll
        for (int off = 16; off > 0; off >>= 1) {
            float ov = __shfl_down_sync(0xffffffffu, mv, off);
            int   oi = __shfl_down_sync(0xffffffffu, mi, off);
            if (ov > mv || (ov == mv && oi < mi)) { mv = ov; mi = oi; }
        }
        if (lane == 0) { swv[w] = mv; swi[w] = mi; }
        __syncthreads();
        if (tid == 0) {
            float bv = swv[0]; int bi = swi[0];
            if (swv[1] > bv || (swv[1] == bv && swi[1] < bi)) { bv = swv[1]; bi = swi[1]; }
            sval[r] = bv; ssel[r] = bi; sidx = bi;
        }
        __syncthreads();
        if (tid == sidx) v = -INFINITY;
    }
    if (tid == 0) {
        float mx = sval[0];
        float w8[8]; float s8 = 0.f;
        #pragma unroll
        for (int r = 0; r < 8; r++) { w8[r] = expf(sval[r] - mx); s8 += w8[r]; }
        float inv = 1.f / s8;
        #pragma unroll
        for (int r = 0; r < 8; r++) {
            g_sel [t*TOPK + r] = ssel[r];
            g_wsel[t*TOPK + r] = w8[r] * inv;
        }
    }
}

// ---------------- routing (exact prefix order), 512 threads ----------------
__global__ __launch_bounds__(512) void route_kernel() {
    const int e = blockIdx.x;
    const int tid = threadIdx.x;
    for (int s = tid; s < CAPE; s += 512) { g_tok[e*CAPE + s] = -1; g_wslot[e*CAPE + s] = 0.f; }
    __shared__ int wsum[16];
    __shared__ int sbase;
    if (tid == 0) sbase = 0;
    __syncthreads();
    const int lane = tid & 31, wid = tid >> 5;
    for (int c = 0; c < T_TOK*TOPK; c += 512) {
        int i = c + tid;
        int ei = g_sel[i];
        bool flag = (ei == e);
        unsigned mask = __ballot_sync(0xffffffffu, flag);
        int wpre = __popc(mask & ((1u << lane) - 1u));
        if (lane == 0) wsum[wid] = __popc(mask);
        __syncthreads();
        int off = 0;
        for (int w = 0; w < wid; w++) off += wsum[w];
        int total = 0;
        for (int w = 0; w < 16; w++) total += wsum[w];
        int pos = sbase + off + wpre;
        if (flag && pos < CAPE) {
            g_tok[e*CAPE + pos] = i / TOPK;
            g_wslot[e*CAPE + pos] = g_wsel[i];
        }
        __syncthreads();
        if (tid == 0) sbase += total;
        __syncthreads();
    }
    if (tid == 0) g_cnt[e] = min(sbase, CAPE);
}

// ================= GEMM1: h = silu(A@Wg)*(A@Wu) =================
// CTA: M=128, N=64 (both G and U), K-chunks of 32, 4-stage cp.async pipeline.
// Stage layout (32KB): AH@0(8K) AL@8192 GH@16384(4K) GL@20480 UH@24576 UL@28672
#define STG 32768
#define G_SMEM (2048 + 4*STG)

__global__ __launch_bounds__(256, 1) void gemm1_kernel() {
    const int e  = blockIdx.z;
    const int m0 = blockIdx.y * 128;
    const int n0 = blockIdx.x * 64;
    if (m0 >= g_cnt[e]) return;

    extern __shared__ __align__(1024) char smem_raw[];
    const uint32_t su = s2u(smem_raw);
    const uint32_t tb = (su + 1024 + 1023) & ~1023u;
    int* sTok = (int*)smem_raw;

    const int tid = threadIdx.x;
    if (tid < 128) sTok[tid] = g_tok[e*CAPE + m0 + tid];
    __syncthreads();

    // staging maps
    const int mA  = tid >> 2, kcA = tid & 3;
    const uint32_t dA0 = sw((uint32_t)(mA*64      + kcA*16));
    const uint32_t dA1 = sw((uint32_t)((mA+64)*64 + kcA*16));
    const int kB = tid >> 3, ncB = tid & 7;
    const uint32_t dB = sw((uint32_t)(kB*128 + ncB*16));
    const int tk0 = sTok[mA], tk1 = sTok[mA+64];
    const int nb0 = tk0 >= 0 ? 16 : 0, nb1 = tk1 >= 0 ? 16 : 0;
    const __nv_bfloat16* ah0 = g_xh + (size_t)(tk0 >= 0 ? tk0 : 0)*HD + kcA*8;
    const __nv_bfloat16* al0 = g_xl + (size_t)(tk0 >= 0 ? tk0 : 0)*HD + kcA*8;
    const __nv_bfloat16* ah1 = g_xh + (size_t)(tk1 >= 0 ? tk1 : 0)*HD + kcA*8;
    const __nv_bfloat16* al1 = g_xl + (size_t)(tk1 >= 0 ? tk1 : 0)*HD + kcA*8;

    auto issue = [&](int it) {
        const int k0 = it * 32;
        const uint32_t sb = tb + (uint32_t)(it & 3) * STG;
        cpa(sb + dA0,        ah0 + k0, nb0);
        cpa(sb + 8192 + dA0, al0 + k0, nb0);
        cpa(sb + dA1,        ah1 + k0, nb1);
        cpa(sb + 8192 + dA1, al1 + k0, nb1);
        const size_t go = ((size_t)e*HD + k0 + kB)*ID + n0 + ncB*8;
        cpa(sb + 16384 + dB, g_wgh + go, 16);
        cpa(sb + 20480 + dB, g_wgl + go, 16);
        cpa(sb + 24576 + dB, g_wuh + go, 16);
        cpa(sb + 28672 + dB, g_wul + go, 16);
        CP_COMMIT();
    };

    const int lane = tid & 31, wid = tid >> 5;
    const int wm = wid >> 1, wn = wid & 1;
    uint32_t offA[2][2], offB[2][2];
    #pragma unroll
    for (int tm = 0; tm < 2; tm++)
        #pragma unroll
        for (int ks = 0; ks < 2; ks++)
            offA[tm][ks] = sw((uint32_t)((wm*32 + tm*16 + (lane & 15))*64 + ks*32 + (lane >> 4)*16));
    #pragma unroll
    for (int ks = 0; ks < 2; ks++)
        #pragma unroll
        for (int nh = 0; nh < 2; nh++)
            offB[ks][nh] = sw((uint32_t)((ks*16 + (lane & 15))*128 + wn*64 + nh*32 + (lane >> 4)*16));

    float cG[2][4][4], cU[2][4][4];
    #pragma unroll
    for (int a = 0; a < 2; a++)
        #pragma unroll
        for (int b = 0; b < 4; b++)
            #pragma unroll
            for (int c = 0; c < 4; c++) { cG[a][b][c] = 0.f; cU[a][b][c] = 0.f; }

    issue(0); issue(1); issue(2);

    #pragma unroll 1
    for (int it = 0; it < HD/32; it++) {
        CP_WAIT2();
        __syncthreads();
        if (it + 3 < HD/32) issue(it + 3);
        else CP_COMMIT();
        const uint32_t sb = tb + (uint32_t)(it & 3) * STG;
        #pragma unroll
        for (int ks = 0; ks < 2; ks++) {
            uint32_t aH[2][4], aL[2][4];
            #pragma unroll
            for (int tm = 0; tm < 2; tm++) {
                ldsm4(aH[tm][0], aH[tm][1], aH[tm][2], aH[tm][3], sb + offA[tm][ks]);
                ldsm4(aL[tm][0], aL[tm][1], aL[tm][2], aL[tm][3], sb + 8192 + offA[tm][ks]);
            }
            {   // G
                uint32_t bh[4][2], bl[4][2];
                #pragma unroll
                for (int nh = 0; nh < 2; nh++) {
                    ldsm4t(bh[nh*2][0], bh[nh*2][1], bh[nh*2+1][0], bh[nh*2+1][1], sb + 16384 + offB[ks][nh]);
                    ldsm4t(bl[nh*2][0], bl[nh*2][1], bl[nh*2+1][0], bl[nh*2+1][1], sb + 20480 + offB[ks][nh]);
                }
                #pragma unroll
                for (int tm = 0; tm < 2; tm++)
                    #pragma unroll
                    for (int tn = 0; tn < 4; tn++) {
                        mma16816(cG[tm][tn], aH[tm], bh[tn]);
                        mma16816(cG[tm][tn], aL[tm], bh[tn]);
                        mma16816(cG[tm][tn], aH[tm], bl[tn]);
                    }
            }
            {   // U
                uint32_t bh[4][2], bl[4][2];
                #pragma unroll
                for (int nh = 0; nh < 2; nh++) {
                    ldsm4t(bh[nh*2][0], bh[nh*2][1], bh[nh*2+1][0], bh[nh*2+1][1], sb + 24576 + offB[ks][nh]);
                    ldsm4t(bl[nh*2][0], bl[nh*2][1], bl[nh*2+1][0], bl[nh*2+1][1], sb + 28672 + offB[ks][nh]);
                }
                #pragma unroll
                for (int tm = 0; tm < 2; tm++)
                    #pragma unroll
                    for (int tn = 0; tn < 4; tn++) {
                        mma16816(cU[tm][tn], aH[tm], bh[tn]);
                        mma16816(cU[tm][tn], aL[tm], bh[tn]);
                        mma16816(cU[tm][tn], aH[tm], bl[tn]);
                    }
            }
        }
    }

    // epilogue: h = silu(G)*U -> bf16 hi/lo
    const int r4 = lane >> 2, cp2 = (lane & 3) * 2;
    #pragma unroll
    for (int tm = 0; tm < 2; tm++)
        #pragma unroll
        for (int tn = 0; tn < 4; tn++) {
            const int row0 = m0 + wm*32 + tm*16 + r4;
            const int col  = n0 + wn*32 + tn*8 + cp2;
            #pragma unroll
            for (int half = 0; half < 2; half++) {
                float g0 = cG[tm][tn][half*2],     u0 = cU[tm][tn][half*2];
                float g1 = cG[tm][tn][half*2 + 1], u1 = cU[tm][tn][half*2 + 1];
                float h0 = g0 / (1.f + __expf(-g0)) * u0;
                float h1 = g1 / (1.f + __expf(-g1)) * u1;
                __nv_bfloat162 hh = __floats2bfloat162_rn(h0, h1);
                __nv_bfloat162 ll = __floats2bfloat162_rn(h0 - __low2float(hh), h1 - __high2float(hh));
                const size_t o = ((size_t)e*CAPE + row0 + half*8)*ID + col;
                *(uint32_t*)(g_hh + o) = *reinterpret_cast<uint32_t*>(&hh);
                *(uint32_t*)(g_hl + o) = *reinterpret_cast<uint32_t*>(&ll);
            }
        }
}

// ================= GEMM2: y += w * (h @ wd), atomic scatter =================
// CTA: M=128, N=128 (2 slabs of 64), 4 stages.
// Stage layout (32KB): AH@0 AL@8192 BH@16384(2 slabs x 4K) BL@24576
__global__ __launch_bounds__(256, 1) void gemm2_kernel(float* __restrict__ y) {
    const int e  = blockIdx.z;
    const int m0 = blockIdx.y * 128;
    const int n0 = blockIdx.x * 128;
    if (m0 >= g_cnt[e]) return;

    extern __shared__ __align__(1024) char smem_raw[];
    const uint32_t su = s2u(smem_raw);
    const uint32_t tb = (su + 1024 + 1023) & ~1023u;
    int*   sTok = (int*)smem_raw;
    float* sW   = (float*)(smem_raw + 512);
    const int tid = threadIdx.x;
    if (tid < 128) {
        sTok[tid] = g_tok  [e*CAPE + m0 + tid];
        sW[tid]   = g_wslot[e*CAPE + m0 + tid];
    }
    __syncthreads();

    const int mA = tid >> 2, kcA = tid & 3;
    const uint32_t dA0 = sw((uint32_t)(mA*64      + kcA*16));
    const uint32_t dA1 = sw((uint32_t)((mA+64)*64 + kcA*16));
    const int kB0 = tid >> 4, ncB0 = tid & 15;
    const uint32_t dB0 = (uint32_t)((ncB0 >> 3)*4096) + sw((uint32_t)(kB0*128 + (ncB0 & 7)*16));
    const uint32_t dB1 = (uint32_t)((ncB0 >> 3)*4096) + sw((uint32_t)((kB0+16)*128 + (ncB0 & 7)*16));

    auto issue = [&](int it) {
        const int k0 = it * 32;
        const uint32_t sb = tb + (uint32_t)(it & 3) * STG;
        const size_t ga0 = ((size_t)e*CAPE + m0 + mA)*ID + k0 + kcA*8;
        const size_t ga1 = ((size_t)e*CAPE + m0 + mA + 64)*ID + k0 + kcA*8;
        cpa(sb + dA0,        g_hh + ga0, 16);
        cpa(sb + 8192 + dA0, g_hl + ga0, 16);
        cpa(sb + dA1,        g_hh + ga1, 16);
        cpa(sb + 8192 + dA1, g_hl + ga1, 16);
        const size_t gb0 = ((size_t)e*ID + k0 + kB0)*HD + n0 + ncB0*8;
        const size_t gb1 = ((size_t)e*ID + k0 + kB0 + 16)*HD + n0 + ncB0*8;
        cpa(sb + 16384 + dB0, g_wdh + gb0, 16);
        cpa(sb + 24576 + dB0, g_wdl + gb0, 16);
        cpa(sb + 16384 + dB1, g_wdh + gb1, 16);
        cpa(sb + 24576 + dB1, g_wdl + gb1, 16);
        CP_COMMIT();
    };

    const int lane = tid & 31, wid = tid >> 5;
    const int wm = wid >> 1, wn = wid & 1;
    uint32_t offA[2][2], offB[2][4];
    #pragma unroll
    for (int tm = 0; tm < 2; tm++)
        #pragma unroll
        for (int ks = 0; ks < 2; ks++)
            offA[tm][ks] = sw((uint32_t)((wm*32 + tm*16 + (lane & 15))*64 + ks*32 + (lane >> 4)*16));
    #pragma unroll
    for (int ks = 0; ks < 2; ks++)
        #pragma unroll
        for (int nh = 0; nh < 4; nh++)
            offB[ks][nh] = (uint32_t)(wn*4096) +
                           sw((uint32_t)((ks*16 + (lane & 15))*128 + nh*32 + (lane >> 4)*16));

    float cc[2][8][4];
    #pragma unroll
    for (int a = 0; a < 2; a++)
        #pragma unroll
        for (int b = 0; b < 8; b++)
            #pragma unroll
            for (int c = 0; c < 4; c++) cc[a][b][c] = 0.f;

    issue(0); issue(1); issue(2);

    #pragma unroll 1
    for (int it = 0; it < ID/32; it++) {
        CP_WAIT2();
        __syncthreads();
        if (it + 3 < ID/32) issue(it + 3);
        else CP_COMMIT();
        const uint32_t sb = tb + (uint32_t)(it & 3) * STG;
        #pragma unroll
        for (int ks = 0; ks < 2; ks++) {
            uint32_t aH[2][4], aL[2][4];
            #pragma unroll
            for (int tm = 0; tm < 2; tm++) {
                ldsm4(aH[tm][0], aH[tm][1], aH[tm][2], aH[tm][3], sb + offA[tm][ks]);
                ldsm4(aL[tm][0], aL[tm][1], aL[tm][2], aL[tm][3], sb + 8192 + offA[tm][ks]);
            }
            uint32_t bh[8][2], bl[8][2];
            #pragma unroll
            for (int nh = 0; nh < 4; nh++) {
                ldsm4t(bh[nh*2][0], bh[nh*2][1], bh[nh*2+1][0], bh[nh*2+1][1], sb + 16384 + offB[ks][nh]);
                ldsm4t(bl[nh*2][0], bl[nh*2][1], bl[nh*2+1][0], bl[nh*2+1][1], sb + 24576 + offB[ks][nh]);
            }
            #pragma unroll
            for (int tm = 0; tm < 2; tm++)
                #pragma unroll
                for (int tn = 0; tn < 8; tn++) {
                    mma16816(cc[tm][tn], aH[tm], bh[tn]);
                    mma16816(cc[tm][tn], aL[tm], bh[tn]);
                    mma16816(cc[tm][tn], aH[tm], bl[tn]);
                }
        }
    }

    // epilogue: scatter-add w * out into y (replaces g_out + combine)
    const int r4 = lane >> 2, cp2 = (lane & 3) * 2;
    #pragma unroll
    for (int tm = 0; tm < 2; tm++)
        #pragma unroll
        for (int half = 0; half < 2; half++) {
            const int rloc = wm*32 + tm*16 + r4 + half*8;
            const int tok = sTok[rloc];
            if (tok < 0) continue;
            const float w = sW[rloc];
            float* yrow = y + (size_t)tok*HD;
            #pragma unroll
            for (int tn = 0; tn < 8; tn++) {
                const int col = n0 + wn*64 + tn*8 + cp2;
                atomicAdd(yrow + col,     w * cc[tm][tn][half*2]);
                atomicAdd(yrow + col + 1, w * cc[tm][tn][half*2 + 1]);
            }
        }
}

// ---------------- launch ----------------
extern "C" void kernel_launch(void* const* d_in, const int* in_sizes, int n_in,
                              void* d_out, int out_size) {
    const float* x      = (const float*)d_in[0];
    const float* gate_w = (const float*)d_in[1];
    const float* wg     = (const float*)d_in[2];
    const float* wu     = (const float*)d_in[3];
    const float* wd     = (const float*)d_in[4];
    float* y = (float*)d_out;

    cudaFuncSetAttribute(gemm1_kernel, cudaFuncAttributeMaxDynamicSharedMemorySize, G_SMEM);
    cudaFuncSetAttribute(gemm2_kernel, cudaFuncAttributeMaxDynamicSharedMemorySize, G_SMEM);

    convert_kernel<<<1024, 256>>>(x,  0, (T_TOK*HD)/4);
    convert_kernel<<<4096, 256>>>(wg, 1, (int)(((size_t)NE*HD*ID)/4));
    convert_kernel<<<4096, 256>>>(wu, 2, (int)(((size_t)NE*HD*ID)/4));
    convert_kernel<<<4096, 256>>>(wd, 3, (int)(((size_t)NE*ID*HD)/4));

    gate_kernel<<<T_TOK/32, 256>>>(x, gate_w);
    topk_kernel<<<T_TOK, 64>>>();
    route_kernel<<<NE, 512>>>();
    zero_y_kernel<<<(T_TOK*HD)/4/256, 256>>>(y);

    gemm1_kernel<<<dim3(ID/64,  CAPE/128, NE), 256, G_SMEM>>>();
    gemm2_kernel<<<dim3(HD/128, CAPE/128, NE), 256, G_SMEM>>>(y);
}

// round 9
// speedup vs baseline: 1.4224x; 1.1215x over previous
#include <cuda_runtime.h>
#include <cuda_bf16.h>
#include <stdint.h>
#include <math.h>

#define T_TOK 2048
#define HD    2048
#define ID    768
#define NE    64
#define TOPK  8
#define CAPE  512

// ---------------- scratch (device globals) ----------------
__device__ int   g_sel [T_TOK*TOPK];
__device__ float g_wsel[T_TOK*TOPK];
__device__ int   g_tok [NE*CAPE];
__device__ float g_wslot[NE*CAPE];
__device__ int   g_cnt [NE];
__device__ float g_logits[T_TOK*NE];
__device__ __nv_bfloat16 g_xh[(size_t)T_TOK*HD],  g_xl[(size_t)T_TOK*HD];
__device__ __nv_bfloat16 g_wgh[(size_t)NE*HD*ID], g_wgl[(size_t)NE*HD*ID];
__device__ __nv_bfloat16 g_wuh[(size_t)NE*HD*ID], g_wul[(size_t)NE*HD*ID];
__device__ __nv_bfloat16 g_wdh[(size_t)NE*ID*HD], g_wdl[(size_t)NE*ID*HD];
__device__ __nv_bfloat16 g_hh [(size_t)NE*CAPE*ID], g_hl[(size_t)NE*CAPE*ID];

// ---------------- helpers ----------------
__device__ __forceinline__ uint32_t s2u(const void* p) {
    uint32_t a;
    asm("{ .reg .u64 t; cvta.to.shared.u64 t, %1; cvt.u32.u64 %0, t; }" : "=r"(a) : "l"(p));
    return a;
}
__device__ __forceinline__ uint32_t sw(uint32_t off) {   // Swizzle<3,4,3> on flat bytes
    return off ^ (((off >> 7) & 7u) << 4);
}
__device__ __forceinline__ void cpa(uint32_t d, const void* s, int nb) {
    asm volatile("cp.async.cg.shared.global [%0], [%1], 16, %2;"
                 :: "r"(d), "l"(s), "r"(nb) : "memory");
}
#define CP_COMMIT() asm volatile("cp.async.commit_group;" ::: "memory")
#define CP_WAIT1()  asm volatile("cp.async.wait_group 1;" ::: "memory")

__device__ __forceinline__ void ldsm4(uint32_t& r0, uint32_t& r1, uint32_t& r2, uint32_t& r3, uint32_t a) {
    asm volatile("ldmatrix.sync.aligned.m8n8.x4.shared.b16 {%0,%1,%2,%3}, [%4];"
                 : "=r"(r0), "=r"(r1), "=r"(r2), "=r"(r3) : "r"(a));
}
__device__ __forceinline__ void ldsm4t(uint32_t& r0, uint32_t& r1, uint32_t& r2, uint32_t& r3, uint32_t a) {
    asm volatile("ldmatrix.sync.aligned.m8n8.x4.trans.shared.b16 {%0,%1,%2,%3}, [%4];"
                 : "=r"(r0), "=r"(r1), "=r"(r2), "=r"(r3) : "r"(a));
}
__device__ __forceinline__ void mma16816(float* c, const uint32_t* a, const uint32_t* b) {
    asm volatile("mma.sync.aligned.m16n8k16.row.col.f32.bf16.bf16.f32 "
                 "{%0,%1,%2,%3}, {%4,%5,%6,%7}, {%8,%9}, {%0,%1,%2,%3};"
                 : "+f"(c[0]), "+f"(c[1]), "+f"(c[2]), "+f"(c[3])
                 : "r"(a[0]), "r"(a[1]), "r"(a[2]), "r"(a[3]), "r"(b[0]), "r"(b[1]));
}

// ---------------- conversion: fp32 -> bf16 hi/lo ----------------
__global__ void convert_kernel(const float* __restrict__ src, int sel, int n4) {
    __nv_bfloat16 *hi, *lo;
    if      (sel == 0) { hi = g_xh;  lo = g_xl;  }
    else if (sel == 1) { hi = g_wgh; lo = g_wgl; }
    else if (sel == 2) { hi = g_wuh; lo = g_wul; }
    else               { hi = g_wdh; lo = g_wdl; }
    for (int i = blockIdx.x*blockDim.x + threadIdx.x; i < n4; i += gridDim.x*blockDim.x) {
        float4 v = ((const float4*)src)[i];
        __nv_bfloat162 a  = __floats2bfloat162_rn(v.x, v.y);
        __nv_bfloat162 b  = __floats2bfloat162_rn(v.z, v.w);
        __nv_bfloat162 ra = __floats2bfloat162_rn(v.x - __low2float(a), v.y - __high2float(a));
        __nv_bfloat162 rb = __floats2bfloat162_rn(v.z - __low2float(b), v.w - __high2float(b));
        ((uint2*)hi)[i] = make_uint2(*reinterpret_cast<uint32_t*>(&a),  *reinterpret_cast<uint32_t*>(&b));
        ((uint2*)lo)[i] = make_uint2(*reinterpret_cast<uint32_t*>(&ra), *reinterpret_cast<uint32_t*>(&rb));
    }
}

// ---------------- zero y ----------------
__global__ void zero_y_kernel(float* __restrict__ y) {
    int i = blockIdx.x*blockDim.x + threadIdx.x;
    ((float4*)y)[i] = make_float4(0.f, 0.f, 0.f, 0.f);
}

// ---------------- gate logits ----------------
__global__ __launch_bounds__(256) void gate_kernel(const float* __restrict__ x,
                                                   const float* __restrict__ gw) {
    const int t0  = blockIdx.x * 32;
    const int tid = threadIdx.x;
    __shared__ float sx[32][33];
    __shared__ float swt[32][65];
    float acc[8];
    #pragma unroll
    for (int i = 0; i < 8; i++) acc[i] = 0.f;
    const int e  = tid & 63;
    const int tb = tid >> 6;
    for (int k0 = 0; k0 < HD; k0 += 32) {
        #pragma unroll
        for (int j = 0; j < 4; j++) {
            int item = tid + j*256;
            int r = item >> 5, c = item & 31;
            sx[r][c] = x[(size_t)(t0 + r)*HD + k0 + c];
        }
        #pragma unroll
        for (int j = 0; j < 8; j++) {
            int item = tid + j*256;
            int ee = item >> 5, hh = item & 31;
            swt[hh][ee] = gw[(size_t)ee*HD + k0 + hh];
        }
        __syncthreads();
        #pragma unroll
        for (int hh = 0; hh < 32; hh++) {
            float wv = swt[hh][e];
            #pragma unroll
            for (int i = 0; i < 8; i++)
                acc[i] += sx[tb*8 + i][hh] * wv;
        }
        __syncthreads();
    }
    #pragma unroll
    for (int i = 0; i < 8; i++)
        g_logits[(size_t)(t0 + tb*8 + i)*NE + e] = acc[i];
}

// ---------------- parallel top-8 (64 threads / token) ----------------
__global__ void topk_kernel() {
    const int t = blockIdx.x, tid = threadIdx.x;
    const int lane = tid & 31, w = tid >> 5;
    float v = g_logits[(size_t)t*NE + tid];
    __shared__ float swv[2];
    __shared__ int   swi[2];
    __shared__ int   sidx;
    __shared__ float sval[8];
    __shared__ int   ssel[8];
    for (int r = 0; r < 8; r++) {
        float mv = v; int mi = tid;
        #pragma unroll
        for (int off = 16; off > 0; off >>= 1) {
            float ov = __shfl_down_sync(0xffffffffu, mv, off);
            int   oi = __shfl_down_sync(0xffffffffu, mi, off);
            if (ov > mv || (ov == mv && oi < mi)) { mv = ov; mi = oi; }
        }
        if (lane == 0) { swv[w] = mv; swi[w] = mi; }
        __syncthreads();
        if (tid == 0) {
            float bv = swv[0]; int bi = swi[0];
            if (swv[1] > bv || (swv[1] == bv && swi[1] < bi)) { bv = swv[1]; bi = swi[1]; }
            sval[r] = bv; ssel[r] = bi; sidx = bi;
        }
        __syncthreads();
        if (tid == sidx) v = -INFINITY;
    }
    if (tid == 0) {
        float mx = sval[0];
        float w8[8]; float s8 = 0.f;
        #pragma unroll
        for (int r = 0; r < 8; r++) { w8[r] = expf(sval[r] - mx); s8 += w8[r]; }
        float inv = 1.f / s8;
        #pragma unroll
        for (int r = 0; r < 8; r++) {
            g_sel [t*TOPK + r] = ssel[r];
            g_wsel[t*TOPK + r] = w8[r] * inv;
        }
    }
}

// ---------------- routing (exact prefix order), 512 threads ----------------
__global__ __launch_bounds__(512) void route_kernel() {
    const int e = blockIdx.x;
    const int tid = threadIdx.x;
    for (int s = tid; s < CAPE; s += 512) { g_tok[e*CAPE + s] = -1; g_wslot[e*CAPE + s] = 0.f; }
    __shared__ int wsum[16];
    __shared__ int sbase;
    if (tid == 0) sbase = 0;
    __syncthreads();
    const int lane = tid & 31, wid = tid >> 5;
    for (int c = 0; c < T_TOK*TOPK; c += 512) {
        int i = c + tid;
        int ei = g_sel[i];
        bool flag = (ei == e);
        unsigned mask = __ballot_sync(0xffffffffu, flag);
        int wpre = __popc(mask & ((1u << lane) - 1u));
        if (lane == 0) wsum[wid] = __popc(mask);
        __syncthreads();
        int off = 0;
        for (int w = 0; w < wid; w++) off += wsum[w];
        int total = 0;
        for (int w = 0; w < 16; w++) total += wsum[w];
        int pos = sbase + off + wpre;
        if (flag && pos < CAPE) {
            g_tok[e*CAPE + pos] = i / TOPK;
            g_wslot[e*CAPE + pos] = g_wsel[i];
        }
        __syncthreads();
        if (tid == 0) sbase += total;
        __syncthreads();
    }
    if (tid == 0) g_cnt[e] = min(sbase, CAPE);
}

// ================= GEMM1: h = silu(A@Wg)*(A@Wu) =================
// CTA: M=128, N=64 (both G and U), K-chunks of 32, 3-stage cp.async, 2 CTAs/SM.
// Stage layout (32KB): AH@0(8K) AL@8192 GH@16384(4K) GL@20480 UH@24576 UL@28672
#define STG 32768
#define G_SMEM (2048 + 3*STG)

__global__ __launch_bounds__(256, 2) void gemm1_kernel() {
    const int e  = blockIdx.z;
    const int m0 = blockIdx.y * 128;
    const int n0 = blockIdx.x * 64;
    if (m0 >= g_cnt[e]) return;

    extern __shared__ __align__(1024) char smem_raw[];
    const uint32_t su = s2u(smem_raw);
    const uint32_t tb = (su + 1024 + 1023) & ~1023u;
    int* sTok = (int*)smem_raw;

    const int tid = threadIdx.x;
    if (tid < 128) sTok[tid] = g_tok[e*CAPE + m0 + tid];
    __syncthreads();

    // staging maps
    const int mA  = tid >> 2, kcA = tid & 3;
    const uint32_t dA0 = sw((uint32_t)(mA*64      + kcA*16));
    const uint32_t dA1 = sw((uint32_t)((mA+64)*64 + kcA*16));
    const int kB = tid >> 3, ncB = tid & 7;
    const uint32_t dB = sw((uint32_t)(kB*128 + ncB*16));
    const int tk0 = sTok[mA], tk1 = sTok[mA+64];
    const int nb0 = tk0 >= 0 ? 16 : 0, nb1 = tk1 >= 0 ? 16 : 0;
    const __nv_bfloat16* ah0 = g_xh + (size_t)(tk0 >= 0 ? tk0 : 0)*HD + kcA*8;
    const __nv_bfloat16* al0 = g_xl + (size_t)(tk0 >= 0 ? tk0 : 0)*HD + kcA*8;
    const __nv_bfloat16* ah1 = g_xh + (size_t)(tk1 >= 0 ? tk1 : 0)*HD + kcA*8;
    const __nv_bfloat16* al1 = g_xl + (size_t)(tk1 >= 0 ? tk1 : 0)*HD + kcA*8;

    auto issue = [&](int it) {
        const int k0 = it * 32;
        const uint32_t sb = tb + (uint32_t)(it % 3) * STG;
        cpa(sb + dA0,        ah0 + k0, nb0);
        cpa(sb + 8192 + dA0, al0 + k0, nb0);
        cpa(sb + dA1,        ah1 + k0, nb1);
        cpa(sb + 8192 + dA1, al1 + k0, nb1);
        const size_t go = ((size_t)e*HD + k0 + kB)*ID + n0 + ncB*8;
        cpa(sb + 16384 + dB, g_wgh + go, 16);
        cpa(sb + 20480 + dB, g_wgl + go, 16);
        cpa(sb + 24576 + dB, g_wuh + go, 16);
        cpa(sb + 28672 + dB, g_wul + go, 16);
        CP_COMMIT();
    };

    const int lane = tid & 31, wid = tid >> 5;
    const int wm = wid >> 1, wn = wid & 1;
    uint32_t offA[2][2], offB[2][2];
    #pragma unroll
    for (int tm = 0; tm < 2; tm++)
        #pragma unroll
        for (int ks = 0; ks < 2; ks++)
            offA[tm][ks] = sw((uint32_t)((wm*32 + tm*16 + (lane & 15))*64 + ks*32 + (lane >> 4)*16));
    #pragma unroll
    for (int ks = 0; ks < 2; ks++)
        #pragma unroll
        for (int nh = 0; nh < 2; nh++)
            offB[ks][nh] = sw((uint32_t)((ks*16 + (lane & 15))*128 + wn*64 + nh*32 + (lane >> 4)*16));

    float cG[2][4][4], cU[2][4][4];
    #pragma unroll
    for (int a = 0; a < 2; a++)
        #pragma unroll
        for (int b = 0; b < 4; b++)
            #pragma unroll
            for (int c = 0; c < 4; c++) { cG[a][b][c] = 0.f; cU[a][b][c] = 0.f; }

    issue(0); issue(1);

    #pragma unroll 1
    for (int it = 0; it < HD/32; it++) {
        CP_WAIT1();
        __syncthreads();
        if (it + 2 < HD/32) issue(it + 2);
        else CP_COMMIT();
        const uint32_t sb = tb + (uint32_t)(it % 3) * STG;
        #pragma unroll
        for (int ks = 0; ks < 2; ks++) {
            uint32_t aH[2][4], aL[2][4];
            #pragma unroll
            for (int tm = 0; tm < 2; tm++) {
                ldsm4(aH[tm][0], aH[tm][1], aH[tm][2], aH[tm][3], sb + offA[tm][ks]);
                ldsm4(aL[tm][0], aL[tm][1], aL[tm][2], aL[tm][3], sb + 8192 + offA[tm][ks]);
            }
            {   // G
                uint32_t bh[4][2], bl[4][2];
                #pragma unroll
                for (int nh = 0; nh < 2; nh++) {
                    ldsm4t(bh[nh*2][0], bh[nh*2][1], bh[nh*2+1][0], bh[nh*2+1][1], sb + 16384 + offB[ks][nh]);
                    ldsm4t(bl[nh*2][0], bl[nh*2][1], bl[nh*2+1][0], bl[nh*2+1][1], sb + 20480 + offB[ks][nh]);
                }
                #pragma unroll
                for (int tm = 0; tm < 2; tm++)
                    #pragma unroll
                    for (int tn = 0; tn < 4; tn++) {
                        mma16816(cG[tm][tn], aH[tm], bh[tn]);
                        mma16816(cG[tm][tn], aL[tm], bh[tn]);
                        mma16816(cG[tm][tn], aH[tm], bl[tn]);
                    }
            }
            {   // U
                uint32_t bh[4][2], bl[4][2];
                #pragma unroll
                for (int nh = 0; nh < 2; nh++) {
                    ldsm4t(bh[nh*2][0], bh[nh*2][1], bh[nh*2+1][0], bh[nh*2+1][1], sb + 24576 + offB[ks][nh]);
                    ldsm4t(bl[nh*2][0], bl[nh*2][1], bl[nh*2+1][0], bl[nh*2+1][1], sb + 28672 + offB[ks][nh]);
                }
                #pragma unroll
                for (int tm = 0; tm < 2; tm++)
                    #pragma unroll
                    for (int tn = 0; tn < 4; tn++) {
                        mma16816(cU[tm][tn], aH[tm], bh[tn]);
                        mma16816(cU[tm][tn], aL[tm], bh[tn]);
                        mma16816(cU[tm][tn], aH[tm], bl[tn]);
                    }
            }
        }
    }

    // epilogue: h = silu(G)*U -> bf16 hi/lo
    const int r4 = lane >> 2, cp2 = (lane & 3) * 2;
    #pragma unroll
    for (int tm = 0; tm < 2; tm++)
        #pragma unroll
        for (int tn = 0; tn < 4; tn++) {
            const int row0 = m0 + wm*32 + tm*16 + r4;
            const int col  = n0 + wn*32 + tn*8 + cp2;
            #pragma unroll
            for (int half = 0; half < 2; half++) {
                float g0 = cG[tm][tn][half*2],     u0 = cU[tm][tn][half*2];
                float g1 = cG[tm][tn][half*2 + 1], u1 = cU[tm][tn][half*2 + 1];
                float h0 = g0 / (1.f + __expf(-g0)) * u0;
                float h1 = g1 / (1.f + __expf(-g1)) * u1;
                __nv_bfloat162 hh = __floats2bfloat162_rn(h0, h1);
                __nv_bfloat162 ll = __floats2bfloat162_rn(h0 - __low2float(hh), h1 - __high2float(hh));
                const size_t o = ((size_t)e*CAPE + row0 + half*8)*ID + col;
                *(uint32_t*)(g_hh + o) = *reinterpret_cast<uint32_t*>(&hh);
                *(uint32_t*)(g_hl + o) = *reinterpret_cast<uint32_t*>(&ll);
            }
        }
}

// ================= GEMM2: y += w * (h @ wd), atomic scatter =================
// CTA: M=128, N=128 (2 slabs of 64), 3 stages, 2 CTAs/SM.
// Stage layout (32KB): AH@0 AL@8192 BH@16384(2 slabs x 4K) BL@24576
__global__ __launch_bounds__(256, 2) void gemm2_kernel(float* __restrict__ y) {
    const int e  = blockIdx.z;
    const int m0 = blockIdx.y * 128;
    const int n0 = blockIdx.x * 128;
    if (m0 >= g_cnt[e]) return;

    extern __shared__ __align__(1024) char smem_raw[];
    const uint32_t su = s2u(smem_raw);
    const uint32_t tb = (su + 1024 + 1023) & ~1023u;
    int*   sTok = (int*)smem_raw;
    float* sW   = (float*)(smem_raw + 512);
    const int tid = threadIdx.x;
    if (tid < 128) {
        sTok[tid] = g_tok  [e*CAPE + m0 + tid];
        sW[tid]   = g_wslot[e*CAPE + m0 + tid];
    }
    __syncthreads();

    const int mA = tid >> 2, kcA = tid & 3;
    const uint32_t dA0 = sw((uint32_t)(mA*64      + kcA*16));
    const uint32_t dA1 = sw((uint32_t)((mA+64)*64 + kcA*16));
    const int kB0 = tid >> 4, ncB0 = tid & 15;
    const uint32_t dB0 = (uint32_t)((ncB0 >> 3)*4096) + sw((uint32_t)(kB0*128 + (ncB0 & 7)*16));
    const uint32_t dB1 = (uint32_t)((ncB0 >> 3)*4096) + sw((uint32_t)((kB0+16)*128 + (ncB0 & 7)*16));

    auto issue = [&](int it) {
        const int k0 = it * 32;
        const uint32_t sb = tb + (uint32_t)(it % 3) * STG;
        const size_t ga0 = ((size_t)e*CAPE + m0 + mA)*ID + k0 + kcA*8;
        const size_t ga1 = ((size_t)e*CAPE + m0 + mA + 64)*ID + k0 + kcA*8;
        cpa(sb + dA0,        g_hh + ga0, 16);
        cpa(sb + 8192 + dA0, g_hl + ga0, 16);
        cpa(sb + dA1,        g_hh + ga1, 16);
        cpa(sb + 8192 + dA1, g_hl + ga1, 16);
        const size_t gb0 = ((size_t)e*ID + k0 + kB0)*HD + n0 + ncB0*8;
        const size_t gb1 = ((size_t)e*ID + k0 + kB0 + 16)*HD + n0 + ncB0*8;
        cpa(sb + 16384 + dB0, g_wdh + gb0, 16);
        cpa(sb + 24576 + dB0, g_wdl + gb0, 16);
        cpa(sb + 16384 + dB1, g_wdh + gb1, 16);
        cpa(sb + 24576 + dB1, g_wdl + gb1, 16);
        CP_COMMIT();
    };

    const int lane = tid & 31, wid = tid >> 5;
    const int wm = wid >> 1, wn = wid & 1;
    uint32_t offA[2][2], offB[2][4];
    #pragma unroll
    for (int tm = 0; tm < 2; tm++)
        #pragma unroll
        for (int ks = 0; ks < 2; ks++)
            offA[tm][ks] = sw((uint32_t)((wm*32 + tm*16 + (lane & 15))*64 + ks*32 + (lane >> 4)*16));
    #pragma unroll
    for (int ks = 0; ks < 2; ks++)
        #pragma unroll
        for (int nh = 0; nh < 4; nh++)
            offB[ks][nh] = (uint32_t)(wn*4096) +
                           sw((uint32_t)((ks*16 + (lane & 15))*128 + nh*32 + (lane >> 4)*16));

    float cc[2][8][4];
    #pragma unroll
    for (int a = 0; a < 2; a++)
        #pragma unroll
        for (int b = 0; b < 8; b++)
            #pragma unroll
            for (int c = 0; c < 4; c++) cc[a][b][c] = 0.f;

    issue(0); issue(1);

    #pragma unroll 1
    for (int it = 0; it < ID/32; it++) {
        CP_WAIT1();
        __syncthreads();
        if (it + 2 < ID/32) issue(it + 2);
        else CP_COMMIT();
        const uint32_t sb = tb + (uint32_t)(it % 3) * STG;
        #pragma unroll
        for (int ks = 0; ks < 2; ks++) {
            uint32_t aH[2][4], aL[2][4];
            #pragma unroll
            for (int tm = 0; tm < 2; tm++) {
                ldsm4(aH[tm][0], aH[tm][1], aH[tm][2], aH[tm][3], sb + offA[tm][ks]);
                ldsm4(aL[tm][0], aL[tm][1], aL[tm][2], aL[tm][3], sb + 8192 + offA[tm][ks]);
            }
            uint32_t bh[8][2], bl[8][2];
            #pragma unroll
            for (int nh = 0; nh < 4; nh++) {
                ldsm4t(bh[nh*2][0], bh[nh*2][1], bh[nh*2+1][0], bh[nh*2+1][1], sb + 16384 + offB[ks][nh]);
                ldsm4t(bl[nh*2][0], bl[nh*2][1], bl[nh*2+1][0], bl[nh*2+1][1], sb + 24576 + offB[ks][nh]);
            }
            #pragma unroll
            for (int tm = 0; tm < 2; tm++)
                #pragma unroll
                for (int tn = 0; tn < 8; tn++) {
                    mma16816(cc[tm][tn], aH[tm], bh[tn]);
                    mma16816(cc[tm][tn], aL[tm], bh[tn]);
                    mma16816(cc[tm][tn], aH[tm], bl[tn]);
                }
        }
    }

    // epilogue: scatter-add w * out into y
    const int r4 = lane >> 2, cp2 = (lane & 3) * 2;
    #pragma unroll
    for (int tm = 0; tm < 2; tm++)
        #pragma unroll
        for (int half = 0; half < 2; half++) {
            const int rloc = wm*32 + tm*16 + r4 + half*8;
            const int tok = sTok[rloc];
            if (tok < 0) continue;
            const float w = sW[rloc];
            float* yrow = y + (size_t)tok*HD;
            #pragma unroll
            for (int tn = 0; tn < 8; tn++) {
                const int col = n0 + wn*64 + tn*8 + cp2;
                atomicAdd(yrow + col,     w * cc[tm][tn][half*2]);
                atomicAdd(yrow + col + 1, w * cc[tm][tn][half*2 + 1]);
            }
        }
}

// ---------------- launch ----------------
extern "C" void kernel_launch(void* const* d_in, const int* in_sizes, int n_in,
                              void* d_out, int out_size) {
    const float* x      = (const float*)d_in[0];
    const float* gate_w = (const float*)d_in[1];
    const float* wg     = (const float*)d_in[2];
    const float* wu     = (const float*)d_in[3];
    const float* wd     = (const float*)d_in[4];
    float* y = (float*)d_out;

    cudaFuncSetAttribute(gemm1_kernel, cudaFuncAttributeMaxDynamicSharedMemorySize, G_SMEM);
    cudaFuncSetAttribute(gemm2_kernel, cudaFuncAttributeMaxDynamicSharedMemorySize, G_SMEM);

    convert_kernel<<<1024, 256>>>(x,  0, (T_TOK*HD)/4);
    convert_kernel<<<4096, 256>>>(wg, 1, (int)(((size_t)NE*HD*ID)/4));
    convert_kernel<<<4096, 256>>>(wu, 2, (int)(((size_t)NE*HD*ID)/4));
    convert_kernel<<<4096, 256>>>(wd, 3, (int)(((size_t)NE*ID*HD)/4));

    gate_kernel<<<T_TOK/32, 256>>>(x, gate_w);
    topk_kernel<<<T_TOK, 64>>>();
    route_kernel<<<NE, 512>>>();
    zero_y_kernel<<<(T_TOK*HD)/4/256, 256>>>(y);

    gemm1_kernel<<<dim3(ID/64,  CAPE/128, NE), 256, G_SMEM>>>();
    gemm2_kernel<<<dim3(HD/128, CAPE/128, NE), 256, G_SMEM>>>(y);
}

// round 10
// speedup vs baseline: 1.9060x; 1.3400x over previous
#include <cuda_runtime.h>
#include <cuda_fp16.h>
#include <stdint.h>
#include <math.h>

#define T_TOK 2048
#define HD    2048
#define ID    768
#define NE    64
#define TOPK  8
#define CAPE  512

// ---------------- scratch (device globals) ----------------
__device__ int   g_sel [T_TOK*TOPK];
__device__ float g_wsel[T_TOK*TOPK];
__device__ int   g_tok [NE*CAPE];
__device__ float g_wslot[NE*CAPE];
__device__ int   g_cnt [NE];
__device__ float g_logits[T_TOK*NE];
__device__ __half g_xh[(size_t)T_TOK*HD],  g_xl[(size_t)T_TOK*HD];
__device__ __half g_wgh[(size_t)NE*HD*ID];
__device__ __half g_wuh[(size_t)NE*HD*ID];
__device__ __half g_wdh[(size_t)NE*ID*HD];
__device__ __half g_hh [(size_t)NE*CAPE*ID], g_hl[(size_t)NE*CAPE*ID];

// ---------------- helpers ----------------
__device__ __forceinline__ uint32_t s2u(const void* p) {
    uint32_t a;
    asm("{ .reg .u64 t; cvta.to.shared.u64 t, %1; cvt.u32.u64 %0, t; }" : "=r"(a) : "l"(p));
    return a;
}
__device__ __forceinline__ uint32_t sw(uint32_t off) {   // Swizzle<3,4,3> on flat bytes
    return off ^ (((off >> 7) & 7u) << 4);
}
__device__ __forceinline__ void cpa(uint32_t d, const void* s, int nb) {
    asm volatile("cp.async.cg.shared.global [%0], [%1], 16, %2;"
                 :: "r"(d), "l"(s), "r"(nb) : "memory");
}
#define CP_COMMIT() asm volatile("cp.async.commit_group;" ::: "memory")
#define CP_WAIT1()  asm volatile("cp.async.wait_group 1;" ::: "memory")

__device__ __forceinline__ void ldsm4(uint32_t& r0, uint32_t& r1, uint32_t& r2, uint32_t& r3, uint32_t a) {
    asm volatile("ldmatrix.sync.aligned.m8n8.x4.shared.b16 {%0,%1,%2,%3}, [%4];"
                 : "=r"(r0), "=r"(r1), "=r"(r2), "=r"(r3) : "r"(a));
}
__device__ __forceinline__ void ldsm4t(uint32_t& r0, uint32_t& r1, uint32_t& r2, uint32_t& r3, uint32_t a) {
    asm volatile("ldmatrix.sync.aligned.m8n8.x4.trans.shared.b16 {%0,%1,%2,%3}, [%4];"
                 : "=r"(r0), "=r"(r1), "=r"(r2), "=r"(r3) : "r"(a));
}
__device__ __forceinline__ void mma16816(float* c, const uint32_t* a, const uint32_t* b) {
    asm volatile("mma.sync.aligned.m16n8k16.row.col.f32.f16.f16.f32 "
                 "{%0,%1,%2,%3}, {%4,%5,%6,%7}, {%8,%9}, {%0,%1,%2,%3};"
                 : "+f"(c[0]), "+f"(c[1]), "+f"(c[2]), "+f"(c[3])
                 : "r"(a[0]), "r"(a[1]), "r"(a[2]), "r"(a[3]), "r"(b[0]), "r"(b[1]));
}

// ---------------- conversion kernels ----------------
// weights: fp32 -> fp16 (hi only)
__global__ void convert_w_kernel(const float* __restrict__ src, int sel, int n4) {
    __half* hi = (sel == 1) ? g_wgh : (sel == 2) ? g_wuh : g_wdh;
    for (int i = blockIdx.x*blockDim.x + threadIdx.x; i < n4; i += gridDim.x*blockDim.x) {
        float4 v = ((const float4*)src)[i];
        __half2 a = __floats2half2_rn(v.x, v.y);
        __half2 b = __floats2half2_rn(v.z, v.w);
        ((uint2*)hi)[i] = make_uint2(*reinterpret_cast<uint32_t*>(&a), *reinterpret_cast<uint32_t*>(&b));
    }
}
// x: fp32 -> fp16 hi + lo
__global__ void convert_x_kernel(const float* __restrict__ src, int n4) {
    for (int i = blockIdx.x*blockDim.x + threadIdx.x; i < n4; i += gridDim.x*blockDim.x) {
        float4 v = ((const float4*)src)[i];
        __half2 a = __floats2half2_rn(v.x, v.y);
        __half2 b = __floats2half2_rn(v.z, v.w);
        __half2 ra = __floats2half2_rn(v.x - __low2float(a), v.y - __high2float(a));
        __half2 rb = __floats2half2_rn(v.z - __low2float(b), v.w - __high2float(b));
        ((uint2*)g_xh)[i] = make_uint2(*reinterpret_cast<uint32_t*>(&a),  *reinterpret_cast<uint32_t*>(&b));
        ((uint2*)g_xl)[i] = make_uint2(*reinterpret_cast<uint32_t*>(&ra), *reinterpret_cast<uint32_t*>(&rb));
    }
}

// ---------------- zero y ----------------
__global__ void zero_y_kernel(float* __restrict__ y) {
    int i = blockIdx.x*blockDim.x + threadIdx.x;
    ((float4*)y)[i] = make_float4(0.f, 0.f, 0.f, 0.f);
}

// ---------------- gate logits ----------------
__global__ __launch_bounds__(256) void gate_kernel(const float* __restrict__ x,
                                                   const float* __restrict__ gw) {
    const int t0  = blockIdx.x * 32;
    const int tid = threadIdx.x;
    __shared__ float sx[32][33];
    __shared__ float swt[32][65];
    float acc[8];
    #pragma unroll
    for (int i = 0; i < 8; i++) acc[i] = 0.f;
    const int e  = tid & 63;
    const int tb = tid >> 6;
    for (int k0 = 0; k0 < HD; k0 += 32) {
        #pragma unroll
        for (int j = 0; j < 4; j++) {
            int item = tid + j*256;
            int r = item >> 5, c = item & 31;
            sx[r][c] = x[(size_t)(t0 + r)*HD + k0 + c];
        }
        #pragma unroll
        for (int j = 0; j < 8; j++) {
            int item = tid + j*256;
            int ee = item >> 5, hh = item & 31;
            swt[hh][ee] = gw[(size_t)ee*HD + k0 + hh];
        }
        __syncthreads();
        #pragma unroll
        for (int hh = 0; hh < 32; hh++) {
            float wv = swt[hh][e];
            #pragma unroll
            for (int i = 0; i < 8; i++)
                acc[i] += sx[tb*8 + i][hh] * wv;
        }
        __syncthreads();
    }
    #pragma unroll
    for (int i = 0; i < 8; i++)
        g_logits[(size_t)(t0 + tb*8 + i)*NE + e] = acc[i];
}

// ---------------- parallel top-8 (64 threads / token) ----------------
__global__ void topk_kernel() {
    const int t = blockIdx.x, tid = threadIdx.x;
    const int lane = tid & 31, w = tid >> 5;
    float v = g_logits[(size_t)t*NE + tid];
    __shared__ float swv[2];
    __shared__ int   swi[2];
    __shared__ int   sidx;
    __shared__ float sval[8];
    __shared__ int   ssel[8];
    for (int r = 0; r < 8; r++) {
        float mv = v; int mi = tid;
        #pragma unroll
        for (int off = 16; off > 0; off >>= 1) {
            float ov = __shfl_down_sync(0xffffffffu, mv, off);
            int   oi = __shfl_down_sync(0xffffffffu, mi, off);
            if (ov > mv || (ov == mv && oi < mi)) { mv = ov; mi = oi; }
        }
        if (lane == 0) { swv[w] = mv; swi[w] = mi; }
        __syncthreads();
        if (tid == 0) {
            float bv = swv[0]; int bi = swi[0];
            if (swv[1] > bv || (swv[1] == bv && swi[1] < bi)) { bv = swv[1]; bi = swi[1]; }
            sval[r] = bv; ssel[r] = bi; sidx = bi;
        }
        __syncthreads();
        if (tid == sidx) v = -INFINITY;
    }
    if (tid == 0) {
        float mx = sval[0];
        float w8[8]; float s8 = 0.f;
        #pragma unroll
        for (int r = 0; r < 8; r++) { w8[r] = expf(sval[r] - mx); s8 += w8[r]; }
        float inv = 1.f / s8;
        #pragma unroll
        for (int r = 0; r < 8; r++) {
            g_sel [t*TOPK + r] = ssel[r];
            g_wsel[t*TOPK + r] = w8[r] * inv;
        }
    }
}

// ---------------- routing (exact prefix order), 512 threads ----------------
__global__ __launch_bounds__(512) void route_kernel() {
    const int e = blockIdx.x;
    const int tid = threadIdx.x;
    for (int s = tid; s < CAPE; s += 512) { g_tok[e*CAPE + s] = -1; g_wslot[e*CAPE + s] = 0.f; }
    __shared__ int wsum[16];
    __shared__ int sbase;
    if (tid == 0) sbase = 0;
    __syncthreads();
    const int lane = tid & 31, wid = tid >> 5;
    for (int c = 0; c < T_TOK*TOPK; c += 512) {
        int i = c + tid;
        int ei = g_sel[i];
        bool flag = (ei == e);
        unsigned mask = __ballot_sync(0xffffffffu, flag);
        int wpre = __popc(mask & ((1u << lane) - 1u));
        if (lane == 0) wsum[wid] = __popc(mask);
        __syncthreads();
        int off = 0;
        for (int w = 0; w < wid; w++) off += wsum[w];
        int total = 0;
        for (int w = 0; w < 16; w++) total += wsum[w];
        int pos = sbase + off + wpre;
        if (flag && pos < CAPE) {
            g_tok[e*CAPE + pos] = i / TOPK;
            g_wslot[e*CAPE + pos] = g_wsel[i];
        }
        __syncthreads();
        if (tid == 0) sbase += total;
        __syncthreads();
    }
    if (tid == 0) g_cnt[e] = min(sbase, CAPE);
}

// ================= GEMM1: h = silu(A@Wg)*(A@Wu), fp16 2-term =================
// CTA: M=128, N=64 per matrix. K-chunks of 32, 3-stage cp.async, 2 CTAs/SM.
// Stage (24KB): AH@0(8K) AL@8192(8K) GH@16384(4K) UH@20480(4K)
#define STG 24576
#define G_SMEM (2048 + 3*STG)

__global__ __launch_bounds__(256, 2) void gemm1_kernel() {
    const int e  = blockIdx.z;
    const int m0 = blockIdx.y * 128;
    const int n0 = blockIdx.x * 64;
    if (m0 >= g_cnt[e]) return;

    extern __shared__ __align__(1024) char smem_raw[];
    const uint32_t su = s2u(smem_raw);
    const uint32_t tb = (su + 1024 + 1023) & ~1023u;
    int* sTok = (int*)smem_raw;

    const int tid = threadIdx.x;
    if (tid < 128) sTok[tid] = g_tok[e*CAPE + m0 + tid];
    __syncthreads();

    // staging maps
    const int mA  = tid >> 2, kcA = tid & 3;
    const uint32_t dA0 = sw((uint32_t)(mA*64      + kcA*16));
    const uint32_t dA1 = sw((uint32_t)((mA+64)*64 + kcA*16));
    const int kB = tid >> 3, ncB = tid & 7;
    const uint32_t dB = sw((uint32_t)(kB*128 + ncB*16));
    const int tk0 = sTok[mA], tk1 = sTok[mA+64];
    const int nb0 = tk0 >= 0 ? 16 : 0, nb1 = tk1 >= 0 ? 16 : 0;
    const __half* ah0 = g_xh + (size_t)(tk0 >= 0 ? tk0 : 0)*HD + kcA*8;
    const __half* al0 = g_xl + (size_t)(tk0 >= 0 ? tk0 : 0)*HD + kcA*8;
    const __half* ah1 = g_xh + (size_t)(tk1 >= 0 ? tk1 : 0)*HD + kcA*8;
    const __half* al1 = g_xl + (size_t)(tk1 >= 0 ? tk1 : 0)*HD + kcA*8;

    auto issue = [&](int it) {
        const int k0 = it * 32;
        const uint32_t sb = tb + (uint32_t)(it % 3) * STG;
        cpa(sb + dA0,        ah0 + k0, nb0);
        cpa(sb + 8192 + dA0, al0 + k0, nb0);
        cpa(sb + dA1,        ah1 + k0, nb1);
        cpa(sb + 8192 + dA1, al1 + k0, nb1);
        const size_t go = ((size_t)e*HD + k0 + kB)*ID + n0 + ncB*8;
        cpa(sb + 16384 + dB, g_wgh + go, 16);
        cpa(sb + 20480 + dB, g_wuh + go, 16);
        CP_COMMIT();
    };

    const int lane = tid & 31, wid = tid >> 5;
    const int wm = wid >> 1, wn = wid & 1;
    uint32_t offA[2][2], offB[2][2];
    #pragma unroll
    for (int tm = 0; tm < 2; tm++)
        #pragma unroll
        for (int ks = 0; ks < 2; ks++)
            offA[tm][ks] = sw((uint32_t)((wm*32 + tm*16 + (lane & 15))*64 + ks*32 + (lane >> 4)*16));
    #pragma unroll
    for (int ks = 0; ks < 2; ks++)
        #pragma unroll
        for (int nh = 0; nh < 2; nh++)
            offB[ks][nh] = sw((uint32_t)((ks*16 + (lane & 15))*128 + wn*64 + nh*32 + (lane >> 4)*16));

    float cG[2][4][4], cU[2][4][4];
    #pragma unroll
    for (int a = 0; a < 2; a++)
        #pragma unroll
        for (int b = 0; b < 4; b++)
            #pragma unroll
            for (int c = 0; c < 4; c++) { cG[a][b][c] = 0.f; cU[a][b][c] = 0.f; }

    issue(0); issue(1);

    #pragma unroll 1
    for (int it = 0; it < HD/32; it++) {
        CP_WAIT1();
        __syncthreads();
        if (it + 2 < HD/32) issue(it + 2);
        else CP_COMMIT();
        const uint32_t sb = tb + (uint32_t)(it % 3) * STG;
        #pragma unroll
        for (int ks = 0; ks < 2; ks++) {
            uint32_t aH[2][4], aL[2][4];
            #pragma unroll
            for (int tm = 0; tm < 2; tm++) {
                ldsm4(aH[tm][0], aH[tm][1], aH[tm][2], aH[tm][3], sb + offA[tm][ks]);
                ldsm4(aL[tm][0], aL[tm][1], aL[tm][2], aL[tm][3], sb + 8192 + offA[tm][ks]);
            }
            uint32_t bg[4][2], bu[4][2];
            #pragma unroll
            for (int nh = 0; nh < 2; nh++) {
                ldsm4t(bg[nh*2][0], bg[nh*2][1], bg[nh*2+1][0], bg[nh*2+1][1], sb + 16384 + offB[ks][nh]);
                ldsm4t(bu[nh*2][0], bu[nh*2][1], bu[nh*2+1][0], bu[nh*2+1][1], sb + 20480 + offB[ks][nh]);
            }
            #pragma unroll
            for (int tm = 0; tm < 2; tm++)
                #pragma unroll
                for (int tn = 0; tn < 4; tn++) {
                    mma16816(cG[tm][tn], aH[tm], bg[tn]);
                    mma16816(cG[tm][tn], aL[tm], bg[tn]);
                    mma16816(cU[tm][tn], aH[tm], bu[tn]);
                    mma16816(cU[tm][tn], aL[tm], bu[tn]);
                }
        }
    }

    // epilogue: h = silu(G)*U -> fp16 hi/lo
    const int r4 = lane >> 2, cp2 = (lane & 3) * 2;
    #pragma unroll
    for (int tm = 0; tm < 2; tm++)
        #pragma unroll
        for (int tn = 0; tn < 4; tn++) {
            const int row0 = m0 + wm*32 + tm*16 + r4;
            const int col  = n0 + wn*32 + tn*8 + cp2;
            #pragma unroll
            for (int half = 0; half < 2; half++) {
                float g0 = cG[tm][tn][half*2],     u0 = cU[tm][tn][half*2];
                float g1 = cG[tm][tn][half*2 + 1], u1 = cU[tm][tn][half*2 + 1];
                float h0 = g0 / (1.f + __expf(-g0)) * u0;
                float h1 = g1 / (1.f + __expf(-g1)) * u1;
                __half2 hh = __floats2half2_rn(h0, h1);
                __half2 ll = __floats2half2_rn(h0 - __low2float(hh), h1 - __high2float(hh));
                const size_t o = ((size_t)e*CAPE + row0 + half*8)*ID + col;
                *(uint32_t*)(g_hh + o) = *reinterpret_cast<uint32_t*>(&hh);
                *(uint32_t*)(g_hl + o) = *reinterpret_cast<uint32_t*>(&ll);
            }
        }
}

// ================= GEMM2: y += w * (h @ wd), fp16 2-term, atomic scatter =================
// CTA: M=128, N=128 (2 slabs of 64), 3 stages, 2 CTAs/SM.
// Stage (24KB): AH@0(8K) AL@8192(8K) BH@16384 (2 slabs x 4K)
__global__ __launch_bounds__(256, 2) void gemm2_kernel(float* __restrict__ y) {
    const int e  = blockIdx.z;
    const int m0 = blockIdx.y * 128;
    const int n0 = blockIdx.x * 128;
    if (m0 >= g_cnt[e]) return;

    extern __shared__ __align__(1024) char smem_raw[];
    const uint32_t su = s2u(smem_raw);
    const uint32_t tb = (su + 1024 + 1023) & ~1023u;
    int*   sTok = (int*)smem_raw;
    float* sW   = (float*)(smem_raw + 512);
    const int tid = threadIdx.x;
    if (tid < 128) {
        sTok[tid] = g_tok  [e*CAPE + m0 + tid];
        sW[tid]   = g_wslot[e*CAPE + m0 + tid];
    }
    __syncthreads();

    const int mA = tid >> 2, kcA = tid & 3;
    const uint32_t dA0 = sw((uint32_t)(mA*64      + kcA*16));
    const uint32_t dA1 = sw((uint32_t)((mA+64)*64 + kcA*16));
    const int kB0 = tid >> 4, ncB0 = tid & 15;
    const uint32_t dB0 = (uint32_t)((ncB0 >> 3)*4096) + sw((uint32_t)(kB0*128 + (ncB0 & 7)*16));
    const uint32_t dB1 = (uint32_t)((ncB0 >> 3)*4096) + sw((uint32_t)((kB0+16)*128 + (ncB0 & 7)*16));

    auto issue = [&](int it) {
        const int k0 = it * 32;
        const uint32_t sb = tb + (uint32_t)(it % 3) * STG;
        const size_t ga0 = ((size_t)e*CAPE + m0 + mA)*ID + k0 + kcA*8;
        const size_t ga1 = ((size_t)e*CAPE + m0 + mA + 64)*ID + k0 + kcA*8;
        cpa(sb + dA0,        g_hh + ga0, 16);
        cpa(sb + 8192 + dA0, g_hl + ga0, 16);
        cpa(sb + dA1,        g_hh + ga1, 16);
        cpa(sb + 8192 + dA1, g_hl + ga1, 16);
        const size_t gb0 = ((size_t)e*ID + k0 + kB0)*HD + n0 + ncB0*8;
        const size_t gb1 = ((size_t)e*ID + k0 + kB0 + 16)*HD + n0 + ncB0*8;
        cpa(sb + 16384 + dB0, g_wdh + gb0, 16);
        cpa(sb + 16384 + dB1, g_wdh + gb1, 16);
        CP_COMMIT();
    };

    const int lane = tid & 31, wid = tid >> 5;
    const int wm = wid >> 1, wn = wid & 1;   // warp tile 32 rows x 64 cols
    uint32_t offA[2][2], offB[2][4];
    #pragma unroll
    for (int tm = 0; tm < 2; tm++)
        #pragma unroll
        for (int ks = 0; ks < 2; ks++)
            offA[tm][ks] = sw((uint32_t)((wm*32 + tm*16 + (lane & 15))*64 + ks*32 + (lane >> 4)*16));
    #pragma unroll
    for (int ks = 0; ks < 2; ks++)
        #pragma unroll
        for (int nh = 0; nh < 4; nh++)
            offB[ks][nh] = (uint32_t)(wn*4096) +
                           sw((uint32_t)((ks*16 + (lane & 15))*128 + nh*32 + (lane >> 4)*16));

    float cc[2][8][4];
    #pragma unroll
    for (int a = 0; a < 2; a++)
        #pragma unroll
        for (int b = 0; b < 8; b++)
            #pragma unroll
            for (int c = 0; c < 4; c++) cc[a][b][c] = 0.f;

    issue(0); issue(1);

    #pragma unroll 1
    for (int it = 0; it < ID/32; it++) {
        CP_WAIT1();
        __syncthreads();
        if (it + 2 < ID/32) issue(it + 2);
        else CP_COMMIT();
        const uint32_t sb = tb + (uint32_t)(it % 3) * STG;
        #pragma unroll
        for (int ks = 0; ks < 2; ks++) {
            uint32_t aH[2][4], aL[2][4];
            #pragma unroll
            for (int tm = 0; tm < 2; tm++) {
                ldsm4(aH[tm][0], aH[tm][1], aH[tm][2], aH[tm][3], sb + offA[tm][ks]);
                ldsm4(aL[tm][0], aL[tm][1], aL[tm][2], aL[tm][3], sb + 8192 + offA[tm][ks]);
            }
            uint32_t bh[8][2];
            #pragma unroll
            for (int nh = 0; nh < 4; nh++) {
                ldsm4t(bh[nh*2][0], bh[nh*2][1], bh[nh*2+1][0], bh[nh*2+1][1], sb + 16384 + offB[ks][nh]);
            }
            #pragma unroll
            for (int tm = 0; tm < 2; tm++)
                #pragma unroll
                for (int tn = 0; tn < 8; tn++) {
                    mma16816(cc[tm][tn], aH[tm], bh[tn]);
                    mma16816(cc[tm][tn], aL[tm], bh[tn]);
                }
        }
    }

    // epilogue: scatter-add w * out into y
    const int r4 = lane >> 2, cp2 = (lane & 3) * 2;
    #pragma unroll
    for (int tm = 0; tm < 2; tm++)
        #pragma unroll
        for (int half = 0; half < 2; half++) {
            const int rloc = wm*32 + tm*16 + r4 + half*8;
            const int tok = sTok[rloc];
            if (tok < 0) continue;
            const float w = sW[rloc];
            float* yrow = y + (size_t)tok*HD;
            #pragma unroll
            for (int tn = 0; tn < 8; tn++) {
                const int col = n0 + wn*64 + tn*8 + cp2;
                atomicAdd(yrow + col,     w * cc[tm][tn][half*2]);
                atomicAdd(yrow + col + 1, w * cc[tm][tn][half*2 + 1]);
            }
        }
}

// ---------------- launch ----------------
extern "C" void kernel_launch(void* const* d_in, const int* in_sizes, int n_in,
                              void* d_out, int out_size) {
    const float* x      = (const float*)d_in[0];
    const float* gate_w = (const float*)d_in[1];
    const float* wg     = (const float*)d_in[2];
    const float* wu     = (const float*)d_in[3];
    const float* wd     = (const float*)d_in[4];
    float* y = (float*)d_out;

    cudaFuncSetAttribute(gemm1_kernel, cudaFuncAttributeMaxDynamicSharedMemorySize, G_SMEM);
    cudaFuncSetAttribute(gemm2_kernel, cudaFuncAttributeMaxDynamicSharedMemorySize, G_SMEM);

    convert_x_kernel<<<1024, 256>>>(x, (T_TOK*HD)/4);
    convert_w_kernel<<<4096, 256>>>(wg, 1, (int)(((size_t)NE*HD*ID)/4));
    convert_w_kernel<<<4096, 256>>>(wu, 2, (int)(((size_t)NE*HD*ID)/4));
    convert_w_kernel<<<4096, 256>>>(wd, 3, (int)(((size_t)NE*ID*HD)/4));

    gate_kernel<<<T_TOK/32, 256>>>(x, gate_w);
    topk_kernel<<<T_TOK, 64>>>();
    route_kernel<<<NE, 512>>>();
    zero_y_kernel<<<(T_TOK*HD)/4/256, 256>>>(y);

    gemm1_kernel<<<dim3(ID/64,  CAPE/128, NE), 256, G_SMEM>>>();
    gemm2_kernel<<<dim3(HD/128, CAPE/128, NE), 256, G_SMEM>>>(y);
}